// round 7
// baseline (speedup 1.0000x reference)
#include <cuda_runtime.h>
#include <cuda_fp16.h>
#include <cstdint>

// ExRestSelfAtten, round 7: fp16 split-precision (hi+lo, 3-chain) warp MMA
// m16n8k16 f32 accum. One CTA/batch (B=1024), 512 threads, 16 warps as 4x4
// grid of 32x32 output tiles. GEMM order: h, k, v, q; q never stored (banded
// scores computed from C fragments).
// Round-6 bugfix: A-fragment k offset now includes the chunk base (cc&3)*32.

#define B_    1024
#define S_    100
#define IN_   100
#define H_    128
#define MID_  32
#define OUT_  2
#define NTHREADS 512

#define SAH 136   // A row stride (halves); word stride 68 -> banks 4g+cq
#define SWH 40    // W-stage row stride (halves); word stride 20 -> distinct banks
#define SKV 132   // K/V row stride (floats)

// SMEM float offsets
#define AH_F   0        // Ah: 128 x 136 halves = 8704 floats; phase3: sctx
#define AL_F   8704     // Al: 8704 floats
#define K_F    17408    // k fp32: 100 x 132
#define V_F    30608    // v fp32: 100 x 132
#define WB_F   43808    // W stage: hi 2560 + lo 2560 floats; phase3: W2 pairs
#define SS_F   48928    // score partials [4][100][8]
#define SBV_F  52128
#define SB2_F  52256
#define SW3_F  52288
#define SB3_F  52352
#define SMEM_FLOATS 52354
#define SMEM_BYTES  (SMEM_FLOATS * 4)

typedef unsigned long long u64;

// prepped weights: [w][hi/lo][kc(4)][512 uint4] ; chunk = 128 n x 32 k halves
__device__ uint4 g_whl[4][2][4][512];

// ---------------- helpers ----------------
__device__ __forceinline__ void fma2(u64& d, u64 a, u64 b) {
    asm volatile("fma.rn.f32x2 %0, %1, %2, %0;" : "+l"(d) : "l"(a), "l"(b));
}
__device__ __forceinline__ u64 pk(float lo, float hi) {
    u64 r; asm("mov.b64 %0, {%1, %2};" : "=l"(r) : "f"(lo), "f"(hi)); return r;
}
__device__ __forceinline__ float2 up(u64 v) {
    float2 r; asm("mov.b64 {%0, %1}, %2;" : "=f"(r.x), "=f"(r.y) : "l"(v)); return r;
}
__device__ __forceinline__ void mma_f16(float* c, const uint32_t* a, const uint32_t* b) {
    asm volatile(
        "mma.sync.aligned.m16n8k16.row.col.f32.f16.f16.f32 "
        "{%0,%1,%2,%3}, {%4,%5,%6,%7}, {%8,%9}, {%0,%1,%2,%3};"
        : "+f"(c[0]), "+f"(c[1]), "+f"(c[2]), "+f"(c[3])
        : "r"(a[0]), "r"(a[1]), "r"(a[2]), "r"(a[3]), "r"(b[0]), "r"(b[1]));
}
__device__ __forceinline__ __half2 split_hi2(float v0, float v1, __half2& lo2) {
    __half h0 = __float2half_rn(v0), h1 = __float2half_rn(v1);
    lo2 = __halves2half2(__float2half_rn(v0 - __half2float(h0)),
                         __float2half_rn(v1 - __half2float(h1)));
    return __halves2half2(h0, h1);
}

// ---------------- prep: W -> fp16 hi/lo, transposed [n][k], chunk-blocked ----
__global__ void prep_weights(const float* __restrict__ W1, const float* __restrict__ Wq,
                             const float* __restrict__ Wk, const float* __restrict__ Wv)
{
    int w = blockIdx.x;
    const float* W = (w == 0) ? W1 : (w == 1) ? Wk : (w == 2) ? Wv : Wq;
    int Kw = (w == 0) ? IN_ : H_;
    __half* dh = (__half*)&g_whl[w][0][0][0];   // [kc][n*32+k]
    __half* dl = (__half*)&g_whl[w][1][0][0];
    for (int e = threadIdx.x; e < 4 * 128 * 32; e += blockDim.x) {
        int kc = e >> 12, rem = e & 4095, n = rem >> 5, k = rem & 31;
        int kg = kc * 32 + k;
        float val = (kg < Kw) ? W[kg * H_ + n] : 0.f;
        __half hh = __float2half_rn(val);
        dh[e] = hh;
        dl[e] = __float2half_rn(val - __half2float(hh));
    }
}

// ---------------- main kernel ----------------
__global__ __launch_bounds__(NTHREADS, 1)
void exrest_fused_kernel(const float* __restrict__ x,  const float* __restrict__ b1,
                         const float* __restrict__ bv, const float* __restrict__ W2,
                         const float* __restrict__ b2, const float* __restrict__ W3,
                         const float* __restrict__ b3, const float* __restrict__ pe,
                         float* __restrict__ out, float* __restrict__ wout)
{
    extern __shared__ float sm[];
    __half* Ah = (__half*)sm;
    __half* Al = (__half*)(sm + AL_F);
    float* smK = sm + K_F;
    float* smV = sm + V_F;
    __half* Wh = (__half*)(sm + WB_F);
    __half* Wl = Wh + 128 * SWH;
    float* smS = sm + SS_F;
    float* sbv = sm + SBV_F;
    float* sb2 = sm + SB2_F;
    float* sW3 = sm + SW3_F;
    float* sb3 = sm + SB3_F;

    const int tid  = threadIdx.x;
    const int lane = tid & 31;
    const int wid  = tid >> 5;
    const int g    = lane >> 2;   // fragment row within 8
    const int cq   = lane & 3;    // thread-in-group
    const int mrow = wid & 3;     // warp m-strip
    const int ncol = wid >> 2;    // warp n-strip
    const int bb   = blockIdx.x;

    // ---- stage consts + x (fp16 hi/lo, padded to 128x128) ----
    if (tid < H_)          sbv[tid] = bv[tid];
    if (tid < MID_)        sb2[tid] = b2[tid];
    if (tid < MID_ * OUT_) sW3[tid] = W3[tid];
    if (tid < OUT_)        sb3[tid] = b3[tid];
    {
        const float* xb = x + (long long)bb * (S_ * IN_);
        for (int e = tid; e < 128 * 64; e += NTHREADS) {
            int r = e >> 6, cp = (e & 63) * 2;
            float v0 = (r < S_ && cp     < IN_) ? xb[r * IN_ + cp]     : 0.f;
            float v1 = (r < S_ && cp + 1 < IN_) ? xb[r * IN_ + cp + 1] : 0.f;
            __half2 lo2;
            __half2 hi2 = split_hi2(v0, v1, lo2);
            *(__half2*)&Ah[r * SAH + cp] = hi2;
            *(__half2*)&Al[r * SAH + cp] = lo2;
        }
    }

    // prefetch weight chunk 0 (hi + lo: one uint4 each per thread)
    uint4 gh = g_whl[0][0][0][tid];
    uint4 gl = g_whl[0][1][0][tid];

    float c[2][4][4];
    #pragma unroll
    for (int mi = 0; mi < 2; mi++)
        #pragma unroll
        for (int nt = 0; nt < 4; nt++)
            #pragma unroll
            for (int rr = 0; rr < 4; rr++) c[mi][nt][rr] = 0.f;

    const float INV_SQRT_H = 0.08838834764831845f;  // 1/sqrt(128)

    for (int cc = 0; cc < 16; cc++) {
        __syncthreads();                       // prev compute + epilogue done
        {   // stage chunk: [n][k] halves at stride 40
            int n = tid >> 2, kq = tid & 3;
            *(uint4*)&Wh[n * SWH + kq * 8] = gh;
            *(uint4*)&Wl[n * SWH + kq * 8] = gl;
        }
        __syncthreads();                       // chunk ready
        if (cc < 15) {
            int nc = cc + 1;
            gh = g_whl[nc >> 2][0][nc & 3][tid];
            gl = g_whl[nc >> 2][1][nc & 3][tid];
        }

        const int kc = cc & 3;
        #pragma unroll
        for (int ks = 0; ks < 2; ks++) {
            const int kaw = (kc * 32 + ks * 16) >> 1;   // A word base (global k)
            const int kbw = ks * 8;                      // B word base (local k)
            uint32_t ah[2][4], al[2][4];
            #pragma unroll
            for (int mi = 0; mi < 2; mi++) {
                const int ro = (mrow * 32 + mi * 16 + g) * (SAH / 2) + kaw + cq;
                const uint32_t* ap = (const uint32_t*)Ah + ro;
                const uint32_t* lp = (const uint32_t*)Al + ro;
                ah[mi][0] = ap[0];
                ah[mi][1] = ap[8 * (SAH / 2)];
                ah[mi][2] = ap[4];
                ah[mi][3] = ap[8 * (SAH / 2) + 4];
                al[mi][0] = lp[0];
                al[mi][1] = lp[8 * (SAH / 2)];
                al[mi][2] = lp[4];
                al[mi][3] = lp[8 * (SAH / 2) + 4];
            }
            uint32_t bh[4][2], bl[4][2];
            #pragma unroll
            for (int nt = 0; nt < 4; nt++) {
                const int bo = (ncol * 32 + nt * 8 + g) * (SWH / 2) + kbw + cq;
                const uint32_t* bp = (const uint32_t*)Wh + bo;
                const uint32_t* qp = (const uint32_t*)Wl + bo;
                bh[nt][0] = bp[0]; bh[nt][1] = bp[4];
                bl[nt][0] = qp[0]; bl[nt][1] = qp[4];
            }
            #pragma unroll
            for (int mi = 0; mi < 2; mi++)
                #pragma unroll
                for (int nt = 0; nt < 4; nt++) {
                    mma_f16(c[mi][nt], ah[mi], bh[nt]);
                    mma_f16(c[mi][nt], ah[mi], bl[nt]);
                    mma_f16(c[mi][nt], al[mi], bh[nt]);
                }
        }

        if ((cc & 3) != 3) continue;
        const int gm = cc >> 2;                // 0:h 1:k 2:v 3:q
        __syncthreads();                       // all reads of A/W done

        if (gm == 0) {
            // h = relu(d + b1) + pe, split fp16 hi/lo, overwrite A in place
            #pragma unroll
            for (int mi = 0; mi < 2; mi++)
                #pragma unroll
                for (int hi = 0; hi < 2; hi++) {
                    int r = mrow * 32 + mi * 16 + hi * 8 + g;
                    if (r < S_) {
                        #pragma unroll
                        for (int nt = 0; nt < 4; nt++) {
                            int col = ncol * 32 + nt * 8 + 2 * cq;
                            float v0 = c[mi][nt][hi * 2 + 0] + b1[col];
                            float v1 = c[mi][nt][hi * 2 + 1] + b1[col + 1];
                            v0 = fmaxf(v0, 0.f) + pe[r * H_ + col];
                            v1 = fmaxf(v1, 0.f) + pe[r * H_ + col + 1];
                            __half2 lo2;
                            __half2 hi2 = split_hi2(v0, v1, lo2);
                            *(__half2*)&Ah[r * SAH + col] = hi2;
                            *(__half2*)&Al[r * SAH + col] = lo2;
                        }
                    }
                }
        } else if (gm == 1 || gm == 2) {
            float* dst = (gm == 1) ? smK : smV;
            #pragma unroll
            for (int mi = 0; mi < 2; mi++)
                #pragma unroll
                for (int hi = 0; hi < 2; hi++) {
                    int r = mrow * 32 + mi * 16 + hi * 8 + g;
                    if (r < S_) {
                        #pragma unroll
                        for (int nt = 0; nt < 4; nt++) {
                            int col = ncol * 32 + nt * 8 + 2 * cq;
                            float v0 = c[mi][nt][hi * 2 + 0];
                            float v1 = c[mi][nt][hi * 2 + 1];
                            if (gm == 2) { v0 += sbv[col]; v1 += sbv[col + 1]; }
                            float2 vv; vv.x = v0; vv.y = v1;
                            *(float2*)&dst[r * SKV + col] = vv;
                        }
                    }
                }
        } else {
            // gm==3: q fragments -> banded score partials per 32-col slice
            #pragma unroll
            for (int mi = 0; mi < 2; mi++)
                #pragma unroll
                for (int hi = 0; hi < 2; hi++) {
                    int r = mrow * 32 + mi * 16 + hi * 8 + g;
                    #pragma unroll
                    for (int m = 0; m < 5; m++) {
                        int j = r + 2 - m;
                        float p = 0.f;
                        if (r < S_ && j >= 0 && j < S_) {
                            const float* kr = smK + j * SKV;
                            #pragma unroll
                            for (int nt = 0; nt < 4; nt++) {
                                int col = ncol * 32 + nt * 8 + 2 * cq;
                                p = fmaf(c[mi][nt][hi * 2 + 0], kr[col],     p);
                                p = fmaf(c[mi][nt][hi * 2 + 1], kr[col + 1], p);
                            }
                        }
                        p += __shfl_xor_sync(0xffffffffu, p, 1);
                        p += __shfl_xor_sync(0xffffffffu, p, 2);
                        if (cq == 0 && r < S_)
                            smS[ncol * 800 + r * 8 + m] = p;
                    }
                }
            // stage W2 K-paired into the (now free) W region
            float2* w2f2 = (float2*)(sm + WB_F);
            for (int e = tid; e < 64 * MID_; e += NTHREADS) {
                int kp = e >> 5, col = e & 31;
                float2 wv;
                wv.x = W2[(2 * kp    ) * MID_ + col];
                wv.y = W2[(2 * kp + 1) * MID_ + col];
                w2f2[e] = wv;
            }
            __syncthreads();
            // one thread per token: reduce partials, softmax, write wout
            if (tid < S_) {
                int s = tid;
                float sc[5];
                #pragma unroll
                for (int m = 0; m < 5; m++)
                    sc[m] = (smS[s * 8 + m] + smS[800 + s * 8 + m]
                           + smS[1600 + s * 8 + m] + smS[2400 + s * 8 + m]) * INV_SQRT_H;
                float mx = sc[0];
                #pragma unroll
                for (int m = 1; m < 5; m++) mx = fmaxf(mx, sc[m]);
                float e5[5], sum = 0.f;
                #pragma unroll
                for (int m = 0; m < 5; m++) { e5[m] = __expf(sc[m] - mx); sum += e5[m]; }
                float rs = 1.f / sum;
                float* wp = wout + ((long long)bb * S_ + s) * 5;
                #pragma unroll
                for (int m = 0; m < 5; m++) {
                    float wmm = e5[m] * rs;
                    wp[m] = wmm;
                    smS[s * 8 + m] = wmm;
                }
            }
            __syncthreads();
        }

        if (gm < 3) {
            #pragma unroll
            for (int mi = 0; mi < 2; mi++)
                #pragma unroll
                for (int nt = 0; nt < 4; nt++)
                    #pragma unroll
                    for (int rr = 0; rr < 4; rr++) c[mi][nt][rr] = 0.f;
        }
    }

    // ---- Phase 3: context + FFN (2 tokens / warp); sctx reuses A region ----
    float* sctx = sm;
    const u64* wbu = (const u64*)(sm + WB_F);
    const float w3a = sW3[lane * 2 + 0];
    const float w3b = sW3[lane * 2 + 1];
    const float b2l = sb2[lane];
    const float b30 = sb3[0], b31 = sb3[1];

    for (int sbt = wid * 2; sbt < S_; sbt += 32) {
        #pragma unroll
        for (int t = 0; t < 2; t++) {
            int s = sbt + t;
            u64 c0 = 0ull, c1 = 0ull;
            #pragma unroll
            for (int m = 0; m < 5; m++) {
                int j = s + 2 - m;
                float wm = smS[s * 8 + m];          // broadcast
                u64 wmp = pk(wm, wm);
                const float* vb = (j >= 0 && j < S_) ? (smV + j * SKV) : sbv;
                const u64* vu = (const u64*)(vb + lane * 4);
                fma2(c0, wmp, vu[0]);
                fma2(c1, wmp, vu[1]);
            }
            u64* cd = (u64*)(sctx + (wid * 2 + t) * H_ + lane * 4);
            cd[0] = c0;
            cd[1] = c1;
        }
        __syncwarp();

        const u64* c0u = (const u64*)(sctx + (wid * 2) * H_);
        const u64* c1u = c0u + 64;
        u64 m0 = 0ull, m1 = 0ull;
        #pragma unroll
        for (int kp = 0; kp < 64; kp += 2) {
            u64 w0 = wbu[ kp      * MID_ + lane];
            u64 w1 = wbu[(kp + 1) * MID_ + lane];
            fma2(m0, c0u[kp],     w0);
            fma2(m0, c0u[kp + 1], w1);
            fma2(m1, c1u[kp],     w0);
            fma2(m1, c1u[kp + 1], w1);
        }

        #pragma unroll
        for (int t = 0; t < 2; t++) {
            int s = sbt + t;
            float2 mm = up(t ? m1 : m0);
            float mid = fmaxf(mm.x + mm.y + b2l, 0.f);
            float p0 = mid * w3a;
            float p1 = mid * w3b;
            #pragma unroll
            for (int off = 16; off > 0; off >>= 1) {
                p0 += __shfl_xor_sync(0xffffffffu, p0, off);
                p1 += __shfl_xor_sync(0xffffffffu, p1, off);
            }
            if (lane == 0) {
                float* op = out + ((long long)bb * S_ + s) * 2;
                op[0] = p0 + b30;
                op[1] = p1 + b31;
            }
        }
        __syncwarp();
    }
}

extern "C" void kernel_launch(void* const* d_in, const int* in_sizes, int n_in,
                              void* d_out, int out_size)
{
    const float* x  = (const float*)d_in[0];
    const float* W1 = (const float*)d_in[1];
    const float* b1 = (const float*)d_in[2];
    const float* Wq = (const float*)d_in[3];
    const float* Wk = (const float*)d_in[4];
    const float* Wv = (const float*)d_in[5];
    const float* bv = (const float*)d_in[6];
    const float* W2 = (const float*)d_in[7];
    const float* b2 = (const float*)d_in[8];
    const float* W3 = (const float*)d_in[9];
    const float* b3 = (const float*)d_in[10];
    const float* pe = (const float*)d_in[11];

    float* out  = (float*)d_out;                    // (B,S,2)
    float* wout = out + (long long)B_ * S_ * OUT_;  // (B,S,1,5)

    cudaFuncSetAttribute(exrest_fused_kernel,
                         cudaFuncAttributeMaxDynamicSharedMemorySize, SMEM_BYTES);

    prep_weights<<<4, 256>>>(W1, Wq, Wk, Wv);
    exrest_fused_kernel<<<B_, NTHREADS, SMEM_BYTES>>>(
        x, b1, bv, W2, b2, W3, b3, pe, out, wout);
}

// round 8
// speedup vs baseline: 1.7633x; 1.7633x over previous
#include <cuda_runtime.h>
#include <cuda_fp16.h>
#include <cstdint>

// ExRestSelfAtten, round 8: 3-GEMM restructure (M = Wq*Wk^T precomputed, so
// scores = (h@M) . h banded and q/k are never materialized), ldmatrix.x4
// fragment loads, double-buffered weight staging (1 barrier/chunk).
// fp16 split-precision (hi+lo, 3-chain) m16n8k16 MMA, f32 accum.
// One CTA/batch (B=1024), 512 threads, 16 warps = 4x4 grid of 32x32 tiles.

#define B_    1024
#define S_    100
#define IN_   100
#define H_    128
#define MID_  32
#define OUT_  2
#define NTHREADS 512

#define SAH 136   // A row stride (halves)
#define SWH 40    // W-stage row stride (halves)

// SMEM float offsets
#define AH_F   0        // Ah 128x136 halves (8704 fl); later v-hi; rows>=S_ unused
#define AL_F   8704     // Al (8704 fl); later v-lo
#define WB_F   17408    // 2 staging buffers x 5120 fl; phase3: sctx + W2 pairs
#define SS_F   27648    // score partials [4][100][8]
#define SBV_F  30848
#define SB2_F  30976
#define SW3_F  31008
#define SB3_F  31072
#define SMEM_FLOATS 31074
#define SMEM_BYTES  (SMEM_FLOATS * 4)

typedef unsigned long long u64;

__device__ float g_M[H_ * H_];                 // Wq @ Wk^T (fp32)
__device__ uint4 g_whl[3][2][4][512];          // [w: W1,M,Wv][hi/lo][kc][...]

// ---------------- helpers ----------------
__device__ __forceinline__ void fma2(u64& d, u64 a, u64 b) {
    asm volatile("fma.rn.f32x2 %0, %1, %2, %0;" : "+l"(d) : "l"(a), "l"(b));
}
__device__ __forceinline__ u64 pk(float lo, float hi) {
    u64 r; asm("mov.b64 %0, {%1, %2};" : "=l"(r) : "f"(lo), "f"(hi)); return r;
}
__device__ __forceinline__ float2 up(u64 v) {
    float2 r; asm("mov.b64 {%0, %1}, %2;" : "=f"(r.x), "=f"(r.y) : "l"(v)); return r;
}
__device__ __forceinline__ uint32_t smem_u32(const void* p) {
    uint32_t a;
    asm("{ .reg .u64 t; cvta.to.shared.u64 t, %1; cvt.u32.u64 %0, t; }" : "=r"(a) : "l"(p));
    return a;
}
__device__ __forceinline__ void mma_f16(float* c, const uint32_t* a, const uint32_t* b) {
    asm volatile(
        "mma.sync.aligned.m16n8k16.row.col.f32.f16.f16.f32 "
        "{%0,%1,%2,%3}, {%4,%5,%6,%7}, {%8,%9}, {%0,%1,%2,%3};"
        : "+f"(c[0]), "+f"(c[1]), "+f"(c[2]), "+f"(c[3])
        : "r"(a[0]), "r"(a[1]), "r"(a[2]), "r"(a[3]), "r"(b[0]), "r"(b[1]));
}
__device__ __forceinline__ void ldm4(uint32_t* r, uint32_t addr) {
    asm volatile("ldmatrix.sync.aligned.m8n8.x4.shared.b16 {%0,%1,%2,%3}, [%4];"
                 : "=r"(r[0]), "=r"(r[1]), "=r"(r[2]), "=r"(r[3]) : "r"(addr));
}
__device__ __forceinline__ __half2 split_hi2(float v0, float v1, __half2& lo2) {
    __half h0 = __float2half_rn(v0), h1 = __float2half_rn(v1);
    lo2 = __halves2half2(__float2half_rn(v0 - __half2float(h0)),
                         __float2half_rn(v1 - __half2float(h1)));
    return __halves2half2(h0, h1);
}

// ---------------- prep 1: M = Wq @ Wk^T ----------------
__global__ void prep_M(const float* __restrict__ Wq, const float* __restrict__ Wk)
{
    __shared__ float qrow[H_];
    int a = blockIdx.x;
    if (threadIdx.x < H_) qrow[threadIdx.x] = Wq[a * H_ + threadIdx.x];
    __syncthreads();
    int b = threadIdx.x;
    float s = 0.f;
    #pragma unroll 8
    for (int c = 0; c < H_; c++) s = fmaf(qrow[c], Wk[b * H_ + c], s);
    g_M[a * H_ + b] = s;
}

// ---------------- prep 2: {W1, M, Wv} -> fp16 hi/lo, [n][k] chunk-blocked ----
__global__ void prep_weights(const float* __restrict__ W1, const float* __restrict__ Wv)
{
    int w = blockIdx.x;                        // 0: W1, 1: M, 2: Wv
    const float* W = (w == 0) ? W1 : (w == 1) ? g_M : Wv;
    int Kw = (w == 0) ? IN_ : H_;
    __half* dh = (__half*)&g_whl[w][0][0][0];
    __half* dl = (__half*)&g_whl[w][1][0][0];
    for (int e = threadIdx.x; e < 4 * 128 * 32; e += blockDim.x) {
        int kc = e >> 12, rem = e & 4095, n = rem >> 5, k = rem & 31;
        int kg = kc * 32 + k;
        float val = (kg < Kw) ? W[kg * H_ + n] : 0.f;
        __half hh = __float2half_rn(val);
        dh[e] = hh;
        dl[e] = __float2half_rn(val - __half2float(hh));
    }
}

// ---------------- main kernel ----------------
__global__ __launch_bounds__(NTHREADS, 1)
void exrest_fused_kernel(const float* __restrict__ x,  const float* __restrict__ b1,
                         const float* __restrict__ bv, const float* __restrict__ W2,
                         const float* __restrict__ b2, const float* __restrict__ W3,
                         const float* __restrict__ b3, const float* __restrict__ pe,
                         float* __restrict__ out, float* __restrict__ wout)
{
    extern __shared__ float sm[];
    __half* Ah = (__half*)sm;
    __half* Al = (__half*)(sm + AL_F);
    const __half2* Ah2 = (const __half2*)sm;
    const __half2* Al2 = (const __half2*)(sm + AL_F);
    float* smS = sm + SS_F;
    float* sbv = sm + SBV_F;
    float* sb2 = sm + SB2_F;
    float* sW3 = sm + SW3_F;
    float* sb3 = sm + SB3_F;

    const int tid  = threadIdx.x;
    const int lane = tid & 31;
    const int wid  = tid >> 5;
    const int g    = lane >> 2;
    const int cq   = lane & 3;
    const int mrow = wid & 3;
    const int ncol = wid >> 2;
    const int bb   = blockIdx.x;

    const uint32_t sbase = smem_u32(sm);
    const uint32_t ALOFSB = AL_F * 4;          // Ah->Al byte delta
    const uint32_t WLOFSB = 2560 * 4;          // stage hi->lo byte delta

    // ---- stage consts + x (fp16 hi/lo, padded to 128x128) ----
    if (tid < H_)          sbv[tid] = bv[tid];
    if (tid < MID_)        sb2[tid] = b2[tid];
    if (tid < MID_ * OUT_) sW3[tid] = W3[tid];
    if (tid < OUT_)        sb3[tid] = b3[tid];
    {
        const float* xb = x + (long long)bb * (S_ * IN_);
        for (int e = tid; e < 128 * 64; e += NTHREADS) {
            int r = e >> 6, cp = (e & 63) * 2;
            float v0 = (r < S_ && cp     < IN_) ? xb[r * IN_ + cp]     : 0.f;
            float v1 = (r < S_ && cp + 1 < IN_) ? xb[r * IN_ + cp + 1] : 0.f;
            __half2 lo2;
            __half2 hi2 = split_hi2(v0, v1, lo2);
            *(__half2*)&Ah[r * SAH + cp] = hi2;
            *(__half2*)&Al[r * SAH + cp] = lo2;
        }
    }

    // ---- prologue: stage chunk 0 into buf 0, prefetch chunk 1 ----
    const int stg_n = tid >> 2, stg_kq = tid & 3;
    uint4 gh = g_whl[0][0][0][tid];
    uint4 gl = g_whl[0][1][0][tid];
    {
        __half* Wn = (__half*)(sm + WB_F);
        *(uint4*)&Wn[stg_n * SWH + stg_kq * 8] = gh;
        *(uint4*)&Wn[128 * SWH + stg_n * SWH + stg_kq * 8] = gl;
    }
    gh = g_whl[0][0][1][tid];
    gl = g_whl[0][1][1][tid];

    float c[2][4][4];
    #pragma unroll
    for (int mi = 0; mi < 2; mi++)
        #pragma unroll
        for (int nt = 0; nt < 4; nt++)
            #pragma unroll
            for (int rr = 0; rr < 4; rr++) c[mi][nt][rr] = 0.f;

    const float INV_SQRT_H = 0.08838834764831845f;

    // per-lane ldmatrix address components
    const uint32_t aRowByte = (uint32_t)((mrow * 32 + (lane & 15)) * SAH
                                         + ((lane >> 4) << 3)) * 2;
    const int bq = lane >> 3;
    const uint32_t bRowHalf = (uint32_t)((ncol * 32 + ((bq >> 1) << 3) + (lane & 7)) * SWH
                                         + ((bq & 1) << 3));

    for (int cc = 0; cc < 12; cc++) {
        __syncthreads();                       // buf[cc&1] ready; buf[(cc+1)&1] free
        const int p = cc & 1;
        if (cc < 11) {
            __half* Wn = (__half*)(sm + WB_F + ((cc + 1) & 1) * 5120);
            *(uint4*)&Wn[stg_n * SWH + stg_kq * 8] = gh;
            *(uint4*)&Wn[128 * SWH + stg_n * SWH + stg_kq * 8] = gl;
            if (cc < 10) {
                int nc = cc + 2;
                gh = g_whl[nc >> 2][0][nc & 3][tid];
                gl = g_whl[nc >> 2][1][nc & 3][tid];
            }
        }

        const int kc = cc & 3;
        const uint32_t wbase = sbase + (uint32_t)WB_F * 4 + (uint32_t)p * 20480;

        #pragma unroll
        for (int ks = 0; ks < 2; ks++) {
            const uint32_t aAddr = sbase + aRowByte + (uint32_t)(kc * 32 + ks * 16) * 2;
            uint32_t ah[2][4], al[2][4];
            ldm4(ah[0], aAddr);
            ldm4(ah[1], aAddr + 16 * SAH * 2);
            ldm4(al[0], aAddr + ALOFSB);
            ldm4(al[1], aAddr + ALOFSB + 16 * SAH * 2);

            const uint32_t bAddr = wbase + (bRowHalf + (uint32_t)(ks * 16)) * 2;
            uint32_t bh[4][2], bl[4][2];
            {
                uint32_t r4[4];
                ldm4(r4, bAddr);
                bh[0][0] = r4[0]; bh[0][1] = r4[1]; bh[1][0] = r4[2]; bh[1][1] = r4[3];
                ldm4(r4, bAddr + 16 * SWH * 2);
                bh[2][0] = r4[0]; bh[2][1] = r4[1]; bh[3][0] = r4[2]; bh[3][1] = r4[3];
                ldm4(r4, bAddr + WLOFSB);
                bl[0][0] = r4[0]; bl[0][1] = r4[1]; bl[1][0] = r4[2]; bl[1][1] = r4[3];
                ldm4(r4, bAddr + WLOFSB + 16 * SWH * 2);
                bl[2][0] = r4[0]; bl[2][1] = r4[1]; bl[3][0] = r4[2]; bl[3][1] = r4[3];
            }
            #pragma unroll
            for (int mi = 0; mi < 2; mi++)
                #pragma unroll
                for (int nt = 0; nt < 4; nt++) {
                    mma_f16(c[mi][nt], ah[mi], bh[nt]);
                    mma_f16(c[mi][nt], ah[mi], bl[nt]);
                    mma_f16(c[mi][nt], al[mi], bh[nt]);
                }
        }

        if ((cc & 3) != 3) continue;
        const int gm = cc >> 2;                // 0: h   1: t (scores)   2: v

        if (gm == 0) {
            __syncthreads();                   // all reads of A done
            #pragma unroll
            for (int mi = 0; mi < 2; mi++)
                #pragma unroll
                for (int hi = 0; hi < 2; hi++) {
                    int r = mrow * 32 + mi * 16 + hi * 8 + g;
                    if (r < S_) {
                        #pragma unroll
                        for (int nt = 0; nt < 4; nt++) {
                            int col = ncol * 32 + nt * 8 + 2 * cq;
                            float v0 = c[mi][nt][hi * 2 + 0] + b1[col];
                            float v1 = c[mi][nt][hi * 2 + 1] + b1[col + 1];
                            v0 = fmaxf(v0, 0.f) + pe[r * H_ + col];
                            v1 = fmaxf(v1, 0.f) + pe[r * H_ + col + 1];
                            __half2 lo2;
                            __half2 hi2 = split_hi2(v0, v1, lo2);
                            *(__half2*)&Ah[r * SAH + col] = hi2;
                            *(__half2*)&Al[r * SAH + col] = lo2;
                        }
                    }
                }
        } else if (gm == 1) {
            // t fragments -> banded scores vs h (reconstructed from Ah+Al)
            #pragma unroll
            for (int mi = 0; mi < 2; mi++)
                #pragma unroll
                for (int hi = 0; hi < 2; hi++) {
                    int r = mrow * 32 + mi * 16 + hi * 8 + g;
                    #pragma unroll
                    for (int m = 0; m < 5; m++) {
                        int j = r + 2 - m;
                        float pf = 0.f;
                        if (r < S_ && j >= 0 && j < S_) {
                            #pragma unroll
                            for (int nt = 0; nt < 4; nt++) {
                                int cw = ncol * 16 + nt * 4 + cq;  // half2 word in row
                                float2 a2 = __half22float2(Ah2[j * 68 + cw]);
                                float2 l2 = __half22float2(Al2[j * 68 + cw]);
                                float hx = a2.x + l2.x, hy = a2.y + l2.y;
                                pf = fmaf(c[mi][nt][hi * 2 + 0], hx, pf);
                                pf = fmaf(c[mi][nt][hi * 2 + 1], hy, pf);
                            }
                        }
                        pf += __shfl_xor_sync(0xffffffffu, pf, 1);
                        pf += __shfl_xor_sync(0xffffffffu, pf, 2);
                        if (cq == 0 && r < S_)
                            smS[ncol * 800 + r * 8 + m] = pf;
                    }
                }
            __syncthreads();
            if (tid < S_) {                    // softmax, write wout + weights
                int s = tid;
                float sc[5];
                #pragma unroll
                for (int m = 0; m < 5; m++)
                    sc[m] = (smS[s * 8 + m] + smS[800 + s * 8 + m]
                           + smS[1600 + s * 8 + m] + smS[2400 + s * 8 + m]) * INV_SQRT_H;
                float mx = sc[0];
                #pragma unroll
                for (int m = 1; m < 5; m++) mx = fmaxf(mx, sc[m]);
                float e5[5], sum = 0.f;
                #pragma unroll
                for (int m = 0; m < 5; m++) { e5[m] = __expf(sc[m] - mx); sum += e5[m]; }
                float rs = 1.f / sum;
                float* wp = wout + ((long long)bb * S_ + s) * 5;
                #pragma unroll
                for (int m = 0; m < 5; m++) {
                    float wmm = e5[m] * rs;
                    wp[m] = wmm;
                    smS[s * 8 + m] = wmm;
                }
            }
            __syncthreads();
        } else {
            __syncthreads();                   // all reads of A (h) done
            // v = c + bv, split hi/lo, overwrite A region
            #pragma unroll
            for (int mi = 0; mi < 2; mi++)
                #pragma unroll
                for (int hi = 0; hi < 2; hi++) {
                    int r = mrow * 32 + mi * 16 + hi * 8 + g;
                    if (r < S_) {
                        #pragma unroll
                        for (int nt = 0; nt < 4; nt++) {
                            int col = ncol * 32 + nt * 8 + 2 * cq;
                            float v0 = c[mi][nt][hi * 2 + 0] + sbv[col];
                            float v1 = c[mi][nt][hi * 2 + 1] + sbv[col + 1];
                            __half2 lo2;
                            __half2 hi2 = split_hi2(v0, v1, lo2);
                            *(__half2*)&Ah[r * SAH + col] = hi2;
                            *(__half2*)&Al[r * SAH + col] = lo2;
                        }
                    }
                }
        }

        if (gm < 2) {
            #pragma unroll
            for (int mi = 0; mi < 2; mi++)
                #pragma unroll
                for (int nt = 0; nt < 4; nt++)
                    #pragma unroll
                    for (int rr = 0; rr < 4; rr++) c[mi][nt][rr] = 0.f;
        }
    }

    // ---- Phase 3: context + FFN (2 tokens / warp) ----
    __syncthreads();
    float* sctx = sm + WB_F;                         // 4096 fl
    float2* w2f2 = (float2*)(sm + WB_F + 4096);      // 2048 fl
    const u64* wbu = (const u64*)(sm + WB_F + 4096);
    for (int e = tid; e < 64 * MID_; e += NTHREADS) {
        int kp = e >> 5, col = e & 31;
        float2 wv;
        wv.x = W2[(2 * kp    ) * MID_ + col];
        wv.y = W2[(2 * kp + 1) * MID_ + col];
        w2f2[e] = wv;
    }
    __syncthreads();

    const float w3a = sW3[lane * 2 + 0];
    const float w3b = sW3[lane * 2 + 1];
    const float b2l = sb2[lane];
    const float b30 = sb3[0], b31 = sb3[1];
    const float bva0 = sbv[lane * 4], bva1 = sbv[lane * 4 + 1];
    const float bvb0 = sbv[lane * 4 + 2], bvb1 = sbv[lane * 4 + 3];

    for (int sbt = wid * 2; sbt < S_; sbt += 32) {
        #pragma unroll
        for (int t = 0; t < 2; t++) {
            int s = sbt + t;
            u64 c0 = 0ull, c1 = 0ull;
            #pragma unroll
            for (int m = 0; m < 5; m++) {
                int j = s + 2 - m;
                float wm = smS[s * 8 + m];
                u64 wmp = pk(wm, wm);
                float2 va, vb2;
                if (j >= 0 && j < S_) {
                    int idx = j * 68 + lane * 2;
                    float2 a0 = __half22float2(Ah2[idx]);
                    float2 l0 = __half22float2(Al2[idx]);
                    float2 a1 = __half22float2(Ah2[idx + 1]);
                    float2 l1 = __half22float2(Al2[idx + 1]);
                    va.x = a0.x + l0.x; va.y = a0.y + l0.y;
                    vb2.x = a1.x + l1.x; vb2.y = a1.y + l1.y;
                } else {
                    va.x = bva0; va.y = bva1;
                    vb2.x = bvb0; vb2.y = bvb1;
                }
                fma2(c0, wmp, pk(va.x, va.y));
                fma2(c1, wmp, pk(vb2.x, vb2.y));
            }
            u64* cd = (u64*)(sctx + (wid * 2 + t) * H_ + lane * 4);
            cd[0] = c0;
            cd[1] = c1;
        }
        __syncwarp();

        const u64* c0u = (const u64*)(sctx + (wid * 2) * H_);
        const u64* c1u = c0u + 64;
        u64 m0 = 0ull, m1 = 0ull;
        #pragma unroll
        for (int kp = 0; kp < 64; kp += 2) {
            u64 w0 = wbu[ kp      * MID_ + lane];
            u64 w1 = wbu[(kp + 1) * MID_ + lane];
            fma2(m0, c0u[kp],     w0);
            fma2(m0, c0u[kp + 1], w1);
            fma2(m1, c1u[kp],     w0);
            fma2(m1, c1u[kp + 1], w1);
        }

        #pragma unroll
        for (int t = 0; t < 2; t++) {
            int s = sbt + t;
            float2 mm = up(t ? m1 : m0);
            float mid = fmaxf(mm.x + mm.y + b2l, 0.f);
            float p0 = mid * w3a;
            float p1 = mid * w3b;
            #pragma unroll
            for (int off = 16; off > 0; off >>= 1) {
                p0 += __shfl_xor_sync(0xffffffffu, p0, off);
                p1 += __shfl_xor_sync(0xffffffffu, p1, off);
            }
            if (lane == 0) {
                float* op = out + ((long long)bb * S_ + s) * 2;
                op[0] = p0 + b30;
                op[1] = p1 + b31;
            }
        }
        __syncwarp();
    }
}

extern "C" void kernel_launch(void* const* d_in, const int* in_sizes, int n_in,
                              void* d_out, int out_size)
{
    const float* x  = (const float*)d_in[0];
    const float* W1 = (const float*)d_in[1];
    const float* b1 = (const float*)d_in[2];
    const float* Wq = (const float*)d_in[3];
    const float* Wk = (const float*)d_in[4];
    const float* Wv = (const float*)d_in[5];
    const float* bv = (const float*)d_in[6];
    const float* W2 = (const float*)d_in[7];
    const float* b2 = (const float*)d_in[8];
    const float* W3 = (const float*)d_in[9];
    const float* b3 = (const float*)d_in[10];
    const float* pe = (const float*)d_in[11];

    float* out  = (float*)d_out;                    // (B,S,2)
    float* wout = out + (long long)B_ * S_ * OUT_;  // (B,S,1,5)

    cudaFuncSetAttribute(exrest_fused_kernel,
                         cudaFuncAttributeMaxDynamicSharedMemorySize, SMEM_BYTES);

    prep_M<<<H_, H_>>>(Wq, Wk);
    prep_weights<<<3, 512>>>(W1, Wv);
    exrest_fused_kernel<<<B_, NTHREADS, SMEM_BYTES>>>(
        x, b1, bv, W2, b2, W3, b3, pe, out, wout);
}

// round 9
// speedup vs baseline: 1.8301x; 1.0379x over previous
#include <cuda_runtime.h>
#include <cuda_fp16.h>
#include <cstdint>

// ExRestSelfAtten, round 9: r8 + (a) dead M-row skip (rows 112-127 tile) with
// SMSP-balanced warp mapping, (b) cp.async weight staging, (c) fast preps.
// 3 GEMMs (h, t=h@M, v), fp16 split hi/lo 3-chain m16n8k16, f32 accum.

#define B_    1024
#define S_    100
#define IN_   100
#define H_    128
#define MID_  32
#define OUT_  2
#define NTHREADS 512

#define SAH 136   // A row stride (halves)
#define SWH 40    // W-stage row stride (halves)

// SMEM float offsets
#define AH_F   0
#define AL_F   8704
#define WB_F   17408    // 2 staging buffers x 5120 fl; phase3: sctx + W2 pairs
#define SS_F   27648    // score partials [4][100][8]
#define SBV_F  30848
#define SB2_F  30976
#define SW3_F  31008
#define SB3_F  31072
#define SMEM_FLOATS 31074
#define SMEM_BYTES  (SMEM_FLOATS * 4)

typedef unsigned long long u64;

__device__ float g_M[H_ * H_];                 // Wq @ Wk^T (fp32)
__device__ uint4 g_whl[3][2][4][512];          // [w: W1,M,Wv][hi/lo][kc][...]

// ---------------- helpers ----------------
__device__ __forceinline__ void fma2(u64& d, u64 a, u64 b) {
    asm volatile("fma.rn.f32x2 %0, %1, %2, %0;" : "+l"(d) : "l"(a), "l"(b));
}
__device__ __forceinline__ u64 pk(float lo, float hi) {
    u64 r; asm("mov.b64 %0, {%1, %2};" : "=l"(r) : "f"(lo), "f"(hi)); return r;
}
__device__ __forceinline__ float2 up(u64 v) {
    float2 r; asm("mov.b64 {%0, %1}, %2;" : "=f"(r.x), "=f"(r.y) : "l"(v)); return r;
}
__device__ __forceinline__ uint32_t smem_u32(const void* p) {
    uint32_t a;
    asm("{ .reg .u64 t; cvta.to.shared.u64 t, %1; cvt.u32.u64 %0, t; }" : "=r"(a) : "l"(p));
    return a;
}
__device__ __forceinline__ void mma_f16(float* c, const uint32_t* a, const uint32_t* b) {
    asm volatile(
        "mma.sync.aligned.m16n8k16.row.col.f32.f16.f16.f32 "
        "{%0,%1,%2,%3}, {%4,%5,%6,%7}, {%8,%9}, {%0,%1,%2,%3};"
        : "+f"(c[0]), "+f"(c[1]), "+f"(c[2]), "+f"(c[3])
        : "r"(a[0]), "r"(a[1]), "r"(a[2]), "r"(a[3]), "r"(b[0]), "r"(b[1]));
}
__device__ __forceinline__ void ldm4(uint32_t* r, uint32_t addr) {
    asm volatile("ldmatrix.sync.aligned.m8n8.x4.shared.b16 {%0,%1,%2,%3}, [%4];"
                 : "=r"(r[0]), "=r"(r[1]), "=r"(r[2]), "=r"(r[3]) : "r"(addr));
}
__device__ __forceinline__ void cp16(uint32_t dst, const void* src) {
    asm volatile("cp.async.ca.shared.global [%0], [%1], 16;" :: "r"(dst), "l"(src) : "memory");
}
__device__ __forceinline__ void cp_commit() {
    asm volatile("cp.async.commit_group;" ::: "memory");
}
__device__ __forceinline__ void cp_wait0() {
    asm volatile("cp.async.wait_group 0;" ::: "memory");
}
__device__ __forceinline__ __half2 split_hi2(float v0, float v1, __half2& lo2) {
    __half h0 = __float2half_rn(v0), h1 = __float2half_rn(v1);
    lo2 = __halves2half2(__float2half_rn(v0 - __half2float(h0)),
                         __float2half_rn(v1 - __half2float(h1)));
    return __halves2half2(h0, h1);
}

// ---------------- prep 1: M = Wq @ Wk^T (coalesced, smem-staged) ----------------
__global__ void prep_M(const float* __restrict__ Wq, const float* __restrict__ Wk)
{
    extern __shared__ float ps[];              // sWk 128x129 + sWq 8x128
    float* sWk = ps;
    float* sWq = ps + 128 * 129;
    const int a0 = blockIdx.x * 8;
    for (int i = threadIdx.x; i < 128 * 128; i += 128) {
        int b = i >> 7, c = i & 127;
        sWk[b * 129 + c] = Wk[i];
    }
    for (int i = threadIdx.x; i < 8 * 128; i += 128)
        sWq[i] = Wq[(a0 + (i >> 7)) * H_ + (i & 127)];
    __syncthreads();
    const int b = threadIdx.x;
    float acc[8];
    #pragma unroll
    for (int a = 0; a < 8; a++) acc[a] = 0.f;
    #pragma unroll 4
    for (int c = 0; c < 128; c++) {
        float wkv = sWk[b * 129 + c];
        #pragma unroll
        for (int a = 0; a < 8; a++) acc[a] = fmaf(sWq[a * 128 + c], wkv, acc[a]);
    }
    #pragma unroll
    for (int a = 0; a < 8; a++) g_M[(a0 + a) * H_ + b] = acc[a];
}

// ---------------- prep 2: {W1, M, Wv} -> fp16 hi/lo [n][k], via smem transpose ----
__global__ void prep_weights(const float* __restrict__ W1, const float* __restrict__ Wv)
{
    __shared__ __half th[32][130], tl[32][130];
    const int w  = blockIdx.x >> 2;            // 0: W1, 1: M, 2: Wv
    const int kc = blockIdx.x & 3;
    const float* W = (w == 0) ? W1 : (w == 1) ? g_M : Wv;
    const int Kw = (w == 0) ? IN_ : H_;
    for (int e = threadIdx.x; e < 32 * 128; e += 256) {
        int kg = e >> 7, n = e & 127;
        int kglob = kc * 32 + kg;
        float val = (kglob < Kw) ? W[kglob * H_ + n] : 0.f;
        __half hh = __float2half_rn(val);
        th[kg][n] = hh;
        tl[kg][n] = __float2half_rn(val - __half2float(hh));
    }
    __syncthreads();
    __half* dh = (__half*)&g_whl[w][0][kc][0];
    __half* dl = (__half*)&g_whl[w][1][kc][0];
    for (int e = threadIdx.x; e < 32 * 128; e += 256) {
        int k = e & 31, n = e >> 5;
        dh[e] = th[k][n];
        dl[e] = tl[k][n];
    }
}

// ---------------- main kernel ----------------
__global__ __launch_bounds__(NTHREADS, 1)
void exrest_fused_kernel(const float* __restrict__ x,  const float* __restrict__ b1,
                         const float* __restrict__ bv, const float* __restrict__ W2,
                         const float* __restrict__ b2, const float* __restrict__ W3,
                         const float* __restrict__ b3, const float* __restrict__ pe,
                         float* __restrict__ out, float* __restrict__ wout)
{
    extern __shared__ float sm[];
    __half* Ah = (__half*)sm;
    __half* Al = (__half*)(sm + AL_F);
    const __half2* Ah2 = (const __half2*)sm;
    const __half2* Al2 = (const __half2*)(sm + AL_F);
    float* smS = sm + SS_F;
    float* sbv = sm + SBV_F;
    float* sb2 = sm + SB2_F;
    float* sW3 = sm + SW3_F;
    float* sb3 = sm + SB3_F;

    const int tid  = threadIdx.x;
    const int lane = tid & 31;
    const int wid  = tid >> 5;
    const int g    = lane >> 2;
    const int cq   = lane & 3;
    const int mrow = wid >> 2;    // SMSP-balanced: light (mrow==3) warps are
    const int ncol = wid & 3;     // wid 12..15 -> one per SMSP
    const bool fullM = (mrow < 3);
    const int bb   = blockIdx.x;

    const uint32_t sbase = smem_u32(sm);
    const uint32_t ALOFSB = AL_F * 4;
    const uint32_t WLOFSB = 2560 * 4;

    // staging dst byte offsets (within a buffer) for this thread
    const int stg_n = tid >> 2, stg_kq = tid & 3;
    const uint32_t stgHiOff = (uint32_t)(stg_n * SWH + stg_kq * 8) * 2;

    // ---- stage consts + x (fp16 hi/lo, padded to 128x128) ----
    if (tid < H_)          sbv[tid] = bv[tid];
    if (tid < MID_)        sb2[tid] = b2[tid];
    if (tid < MID_ * OUT_) sW3[tid] = W3[tid];
    if (tid < OUT_)        sb3[tid] = b3[tid];
    {
        const float* xb = x + (long long)bb * (S_ * IN_);
        for (int e = tid; e < 128 * 64; e += NTHREADS) {
            int r = e >> 6, cp = (e & 63) * 2;
            float v0 = (r < S_ && cp     < IN_) ? xb[r * IN_ + cp]     : 0.f;
            float v1 = (r < S_ && cp + 1 < IN_) ? xb[r * IN_ + cp + 1] : 0.f;
            __half2 lo2;
            __half2 hi2 = split_hi2(v0, v1, lo2);
            *(__half2*)&Ah[r * SAH + cp] = hi2;
            *(__half2*)&Al[r * SAH + cp] = lo2;
        }
    }

    // ---- prologue: cp.async chunk 0 into buf 0 ----
    {
        uint32_t d = sbase + WB_F * 4 + stgHiOff;
        cp16(d,          &g_whl[0][0][0][tid]);
        cp16(d + WLOFSB, &g_whl[0][1][0][tid]);
        cp_commit();
        cp_wait0();
    }
    __syncthreads();

    float c[2][4][4];
    #pragma unroll
    for (int mi = 0; mi < 2; mi++)
        #pragma unroll
        for (int nt = 0; nt < 4; nt++)
            #pragma unroll
            for (int rr = 0; rr < 4; rr++) c[mi][nt][rr] = 0.f;

    const float INV_SQRT_H = 0.08838834764831845f;

    const uint32_t aRowByte = (uint32_t)((mrow * 32 + (lane & 15)) * SAH
                                         + ((lane >> 4) << 3)) * 2;
    const int bq = lane >> 3;
    const uint32_t bRowHalf = (uint32_t)((ncol * 32 + ((bq >> 1) << 3) + (lane & 7)) * SWH
                                         + ((bq & 1) << 3));

    for (int cc = 0; cc < 12; cc++) {
        const int p = cc & 1;
        if (cc < 11) {                         // cp.async next chunk -> other buf
            int nc = cc + 1;
            uint32_t d = sbase + WB_F * 4 + (uint32_t)(1 - p) * 20480 + stgHiOff;
            cp16(d,          &g_whl[nc >> 2][0][nc & 3][tid]);
            cp16(d + WLOFSB, &g_whl[nc >> 2][1][nc & 3][tid]);
            cp_commit();
        }

        const int kc = cc & 3;
        const uint32_t wbase = sbase + (uint32_t)WB_F * 4 + (uint32_t)p * 20480;

        #pragma unroll
        for (int ks = 0; ks < 2; ks++) {
            const uint32_t aAddr = sbase + aRowByte + (uint32_t)(kc * 32 + ks * 16) * 2;
            uint32_t ah[2][4], al[2][4];
            ldm4(ah[0], aAddr);
            ldm4(al[0], aAddr + ALOFSB);
            if (fullM) {
                ldm4(ah[1], aAddr + 16 * SAH * 2);
                ldm4(al[1], aAddr + ALOFSB + 16 * SAH * 2);
            }

            const uint32_t bAddr = wbase + (bRowHalf + (uint32_t)(ks * 16)) * 2;
            uint32_t bh[4][2], bl[4][2];
            {
                uint32_t r4[4];
                ldm4(r4, bAddr);
                bh[0][0] = r4[0]; bh[0][1] = r4[1]; bh[1][0] = r4[2]; bh[1][1] = r4[3];
                ldm4(r4, bAddr + 16 * SWH * 2);
                bh[2][0] = r4[0]; bh[2][1] = r4[1]; bh[3][0] = r4[2]; bh[3][1] = r4[3];
                ldm4(r4, bAddr + WLOFSB);
                bl[0][0] = r4[0]; bl[0][1] = r4[1]; bl[1][0] = r4[2]; bl[1][1] = r4[3];
                ldm4(r4, bAddr + WLOFSB + 16 * SWH * 2);
                bl[2][0] = r4[0]; bl[2][1] = r4[1]; bl[3][0] = r4[2]; bl[3][1] = r4[3];
            }
            #pragma unroll
            for (int nt = 0; nt < 4; nt++) {
                mma_f16(c[0][nt], ah[0], bh[nt]);
                mma_f16(c[0][nt], ah[0], bl[nt]);
                mma_f16(c[0][nt], al[0], bh[nt]);
            }
            if (fullM) {
                #pragma unroll
                for (int nt = 0; nt < 4; nt++) {
                    mma_f16(c[1][nt], ah[1], bh[nt]);
                    mma_f16(c[1][nt], ah[1], bl[nt]);
                    mma_f16(c[1][nt], al[1], bh[nt]);
                }
            }
        }

        if ((cc & 3) == 3) {
            const int gm = cc >> 2;            // 0: h   1: t (scores)   2: v

            if (gm == 0) {
                __syncthreads();               // all ldmatrix reads of A done
                #pragma unroll
                for (int mi = 0; mi < 2; mi++)
                    #pragma unroll
                    for (int hi = 0; hi < 2; hi++) {
                        int r = mrow * 32 + mi * 16 + hi * 8 + g;
                        if (r < S_) {
                            #pragma unroll
                            for (int nt = 0; nt < 4; nt++) {
                                int col = ncol * 32 + nt * 8 + 2 * cq;
                                float v0 = c[mi][nt][hi * 2 + 0] + b1[col];
                                float v1 = c[mi][nt][hi * 2 + 1] + b1[col + 1];
                                v0 = fmaxf(v0, 0.f) + pe[r * H_ + col];
                                v1 = fmaxf(v1, 0.f) + pe[r * H_ + col + 1];
                                __half2 lo2;
                                __half2 hi2 = split_hi2(v0, v1, lo2);
                                *(__half2*)&Ah[r * SAH + col] = hi2;
                                *(__half2*)&Al[r * SAH + col] = lo2;
                            }
                        }
                    }
            } else if (gm == 1) {
                // t fragments -> banded scores vs h
                #pragma unroll
                for (int mi = 0; mi < 2; mi++)
                    #pragma unroll
                    for (int hi = 0; hi < 2; hi++) {
                        int r = mrow * 32 + mi * 16 + hi * 8 + g;
                        #pragma unroll
                        for (int m = 0; m < 5; m++) {
                            int j = r + 2 - m;
                            float pf = 0.f;
                            if (r < S_ && j >= 0 && j < S_) {
                                #pragma unroll
                                for (int nt = 0; nt < 4; nt++) {
                                    int cw = ncol * 16 + nt * 4 + cq;
                                    float2 a2 = __half22float2(Ah2[j * 68 + cw]);
                                    float2 l2 = __half22float2(Al2[j * 68 + cw]);
                                    pf = fmaf(c[mi][nt][hi * 2 + 0], a2.x + l2.x, pf);
                                    pf = fmaf(c[mi][nt][hi * 2 + 1], a2.y + l2.y, pf);
                                }
                            }
                            pf += __shfl_xor_sync(0xffffffffu, pf, 1);
                            pf += __shfl_xor_sync(0xffffffffu, pf, 2);
                            if (cq == 0 && r < S_)
                                smS[ncol * 800 + r * 8 + m] = pf;
                        }
                    }
                __syncthreads();
                if (tid < S_) {
                    int s = tid;
                    float sc[5];
                    #pragma unroll
                    for (int m = 0; m < 5; m++)
                        sc[m] = (smS[s * 8 + m] + smS[800 + s * 8 + m]
                               + smS[1600 + s * 8 + m] + smS[2400 + s * 8 + m]) * INV_SQRT_H;
                    float mx = sc[0];
                    #pragma unroll
                    for (int m = 1; m < 5; m++) mx = fmaxf(mx, sc[m]);
                    float e5[5], sum = 0.f;
                    #pragma unroll
                    for (int m = 0; m < 5; m++) { e5[m] = __expf(sc[m] - mx); sum += e5[m]; }
                    float rs = 1.f / sum;
                    float* wp = wout + ((long long)bb * S_ + s) * 5;
                    #pragma unroll
                    for (int m = 0; m < 5; m++) {
                        float wmm = e5[m] * rs;
                        wp[m] = wmm;
                        smS[s * 8 + m] = wmm;
                    }
                }
            } else {
                __syncthreads();               // all chunk-11 reads of A done
                #pragma unroll
                for (int mi = 0; mi < 2; mi++)
                    #pragma unroll
                    for (int hi = 0; hi < 2; hi++) {
                        int r = mrow * 32 + mi * 16 + hi * 8 + g;
                        if (r < S_) {
                            #pragma unroll
                            for (int nt = 0; nt < 4; nt++) {
                                int col = ncol * 32 + nt * 8 + 2 * cq;
                                float v0 = c[mi][nt][hi * 2 + 0] + sbv[col];
                                float v1 = c[mi][nt][hi * 2 + 1] + sbv[col + 1];
                                __half2 lo2;
                                __half2 hi2 = split_hi2(v0, v1, lo2);
                                *(__half2*)&Ah[r * SAH + col] = hi2;
                                *(__half2*)&Al[r * SAH + col] = lo2;
                            }
                        }
                    }
            }

            if (gm < 2) {
                #pragma unroll
                for (int mi = 0; mi < 2; mi++)
                    #pragma unroll
                    for (int nt = 0; nt < 4; nt++)
                        #pragma unroll
                        for (int rr = 0; rr < 4; rr++) c[mi][nt][rr] = 0.f;
            }
        }

        cp_wait0();
        __syncthreads();                       // next buf ready + A writes visible
    }

    // ---- Phase 3: context + FFN (2 tokens / warp) ----
    float* sctx = sm + WB_F;
    float2* w2f2 = (float2*)(sm + WB_F + 4096);
    const u64* wbu = (const u64*)(sm + WB_F + 4096);
    for (int e = tid; e < 64 * MID_; e += NTHREADS) {
        int kp = e >> 5, col = e & 31;
        float2 wv;
        wv.x = W2[(2 * kp    ) * MID_ + col];
        wv.y = W2[(2 * kp + 1) * MID_ + col];
        w2f2[e] = wv;
    }
    __syncthreads();

    const float w3a = sW3[lane * 2 + 0];
    const float w3b = sW3[lane * 2 + 1];
    const float b2l = sb2[lane];
    const float b30 = sb3[0], b31 = sb3[1];
    const float bva0 = sbv[lane * 4], bva1 = sbv[lane * 4 + 1];
    const float bvb0 = sbv[lane * 4 + 2], bvb1 = sbv[lane * 4 + 3];

    for (int sbt = wid * 2; sbt < S_; sbt += 32) {
        #pragma unroll
        for (int t = 0; t < 2; t++) {
            int s = sbt + t;
            u64 c0 = 0ull, c1 = 0ull;
            #pragma unroll
            for (int m = 0; m < 5; m++) {
                int j = s + 2 - m;
                float wm = smS[s * 8 + m];
                u64 wmp = pk(wm, wm);
                float2 va, vb2;
                if (j >= 0 && j < S_) {
                    int idx = j * 68 + lane * 2;
                    float2 a0 = __half22float2(Ah2[idx]);
                    float2 l0 = __half22float2(Al2[idx]);
                    float2 a1 = __half22float2(Ah2[idx + 1]);
                    float2 l1 = __half22float2(Al2[idx + 1]);
                    va.x = a0.x + l0.x; va.y = a0.y + l0.y;
                    vb2.x = a1.x + l1.x; vb2.y = a1.y + l1.y;
                } else {
                    va.x = bva0; va.y = bva1;
                    vb2.x = bvb0; vb2.y = bvb1;
                }
                fma2(c0, wmp, pk(va.x, va.y));
                fma2(c1, wmp, pk(vb2.x, vb2.y));
            }
            u64* cd = (u64*)(sctx + (wid * 2 + t) * H_ + lane * 4);
            cd[0] = c0;
            cd[1] = c1;
        }
        __syncwarp();

        const u64* c0u = (const u64*)(sctx + (wid * 2) * H_);
        const u64* c1u = c0u + 64;
        u64 m0 = 0ull, m1 = 0ull;
        #pragma unroll
        for (int kp = 0; kp < 64; kp += 2) {
            u64 w0 = wbu[ kp      * MID_ + lane];
            u64 w1 = wbu[(kp + 1) * MID_ + lane];
            fma2(m0, c0u[kp],     w0);
            fma2(m0, c0u[kp + 1], w1);
            fma2(m1, c1u[kp],     w0);
            fma2(m1, c1u[kp + 1], w1);
        }

        #pragma unroll
        for (int t = 0; t < 2; t++) {
            int s = sbt + t;
            float2 mm = up(t ? m1 : m0);
            float mid = fmaxf(mm.x + mm.y + b2l, 0.f);
            float p0 = mid * w3a;
            float p1 = mid * w3b;
            #pragma unroll
            for (int off = 16; off > 0; off >>= 1) {
                p0 += __shfl_xor_sync(0xffffffffu, p0, off);
                p1 += __shfl_xor_sync(0xffffffffu, p1, off);
            }
            if (lane == 0) {
                float* op = out + ((long long)bb * S_ + s) * 2;
                op[0] = p0 + b30;
                op[1] = p1 + b31;
            }
        }
        __syncwarp();
    }
}

extern "C" void kernel_launch(void* const* d_in, const int* in_sizes, int n_in,
                              void* d_out, int out_size)
{
    const float* x  = (const float*)d_in[0];
    const float* W1 = (const float*)d_in[1];
    const float* b1 = (const float*)d_in[2];
    const float* Wq = (const float*)d_in[3];
    const float* Wk = (const float*)d_in[4];
    const float* Wv = (const float*)d_in[5];
    const float* bv = (const float*)d_in[6];
    const float* W2 = (const float*)d_in[7];
    const float* b2 = (const float*)d_in[8];
    const float* W3 = (const float*)d_in[9];
    const float* b3 = (const float*)d_in[10];
    const float* pe = (const float*)d_in[11];

    float* out  = (float*)d_out;                    // (B,S,2)
    float* wout = out + (long long)B_ * S_ * OUT_;  // (B,S,1,5)

    const int PREP_M_SMEM = (128 * 129 + 8 * 128) * 4;
    cudaFuncSetAttribute(prep_M, cudaFuncAttributeMaxDynamicSharedMemorySize, PREP_M_SMEM);
    cudaFuncSetAttribute(exrest_fused_kernel,
                         cudaFuncAttributeMaxDynamicSharedMemorySize, SMEM_BYTES);

    prep_M<<<16, 128, PREP_M_SMEM>>>(Wq, Wk);
    prep_weights<<<12, 256>>>(W1, Wv);
    exrest_fused_kernel<<<B_, NTHREADS, SMEM_BYTES>>>(
        x, b1, bv, W2, b2, W3, b3, pe, out, wout);
}

// round 11
// speedup vs baseline: 2.1729x; 1.1873x over previous
#include <cuda_runtime.h>
#include <cuda_fp16.h>
#include <cstdint>

// ExRestSelfAtten, round 10: 2 CTAs/SM (256 thr, smem ~109KB, regs<=128),
// smS overlaid on dead A rows, fast thread-per-output prep_M.
// 3 GEMMs (h, t=h@M, v), fp16 split hi/lo 3-chain m16n8k16, f32 accum.

#define B_    1024
#define S_    100
#define IN_   100
#define H_    128
#define MID_  32
#define OUT_  2
#define NTHREADS 256

#define SAH 136   // A row stride (halves)
#define SWH 40    // W-stage row stride (halves)

// SMEM float offsets
#define AH_F   0        // Ah 128x136 halves = 8704 fl; rows 100-127 tail = smS
#define AL_F   8704
#define WB_F   17408    // 2 staging buffers x 5120 fl; phase3: sctx + W2 pairs
#define SBV_F  27648
#define SB2_F  27776
#define SW3_F  27808
#define SB3_F  27872
#define SMEM_FLOATS 27874
#define SMEM_BYTES  (SMEM_FLOATS * 4)

#define SMS_F  6800     // smS overlay: Ah rows 100..127 => floats [6800, 8704)
                        // need [2][100][8] = 1600 fl < 1904 avail

typedef unsigned long long u64;

__device__ float g_M[H_ * H_];                 // Wq @ Wk^T (fp32)
__device__ uint4 g_whl[3][2][4][512];          // [w: W1,M,Wv][hi/lo][kc][...]

// ---------------- helpers ----------------
__device__ __forceinline__ void fma2(u64& d, u64 a, u64 b) {
    asm volatile("fma.rn.f32x2 %0, %1, %2, %0;" : "+l"(d) : "l"(a), "l"(b));
}
__device__ __forceinline__ u64 pk(float lo, float hi) {
    u64 r; asm("mov.b64 %0, {%1, %2};" : "=l"(r) : "f"(lo), "f"(hi)); return r;
}
__device__ __forceinline__ float2 up(u64 v) {
    float2 r; asm("mov.b64 {%0, %1}, %2;" : "=f"(r.x), "=f"(r.y) : "l"(v)); return r;
}
__device__ __forceinline__ uint32_t smem_u32(const void* p) {
    uint32_t a;
    asm("{ .reg .u64 t; cvta.to.shared.u64 t, %1; cvt.u32.u64 %0, t; }" : "=r"(a) : "l"(p));
    return a;
}
__device__ __forceinline__ void mma_f16(float* c, const uint32_t* a,
                                        uint32_t b0, uint32_t b1) {
    asm volatile(
        "mma.sync.aligned.m16n8k16.row.col.f32.f16.f16.f32 "
        "{%0,%1,%2,%3}, {%4,%5,%6,%7}, {%8,%9}, {%0,%1,%2,%3};"
        : "+f"(c[0]), "+f"(c[1]), "+f"(c[2]), "+f"(c[3])
        : "r"(a[0]), "r"(a[1]), "r"(a[2]), "r"(a[3]), "r"(b0), "r"(b1));
}
__device__ __forceinline__ void ldm4(uint32_t* r, uint32_t addr) {
    asm volatile("ldmatrix.sync.aligned.m8n8.x4.shared.b16 {%0,%1,%2,%3}, [%4];"
                 : "=r"(r[0]), "=r"(r[1]), "=r"(r[2]), "=r"(r[3]) : "r"(addr));
}
__device__ __forceinline__ void cp16(uint32_t dst, const void* src) {
    asm volatile("cp.async.ca.shared.global [%0], [%1], 16;" :: "r"(dst), "l"(src) : "memory");
}
__device__ __forceinline__ void cp_commit() {
    asm volatile("cp.async.commit_group;" ::: "memory");
}
__device__ __forceinline__ void cp_wait0() {
    asm volatile("cp.async.wait_group 0;" ::: "memory");
}
__device__ __forceinline__ __half2 split_hi2(float v0, float v1, __half2& lo2) {
    __half h0 = __float2half_rn(v0), h1 = __float2half_rn(v1);
    lo2 = __halves2half2(__float2half_rn(v0 - __half2float(h0)),
                         __float2half_rn(v1 - __half2float(h1)));
    return __halves2half2(h0, h1);
}

// ---------------- prep 1: M = Wq @ Wk^T, thread-per-output ----------------
__global__ void prep_M(const float* __restrict__ Wq, const float* __restrict__ Wk)
{
    const int idx = blockIdx.x * 256 + threadIdx.x;   // 64 blocks -> 16384
    const int a = idx >> 7, n = idx & 127;
    const float4* wq = (const float4*)(Wq + a * H_);  // warp-uniform (broadcast)
    const float4* wk = (const float4*)(Wk + n * H_);  // per-thread sequential
    float s0 = 0.f, s1 = 0.f, s2 = 0.f, s3 = 0.f;
    #pragma unroll 8
    for (int i = 0; i < 32; i++) {
        float4 q = wq[i], k = wk[i];
        s0 = fmaf(q.x, k.x, s0);
        s1 = fmaf(q.y, k.y, s1);
        s2 = fmaf(q.z, k.z, s2);
        s3 = fmaf(q.w, k.w, s3);
    }
    g_M[a * H_ + n] = (s0 + s1) + (s2 + s3);
}

// ---------------- prep 2: {W1, M, Wv} -> fp16 hi/lo [n][k], smem transpose ----
__global__ void prep_weights(const float* __restrict__ W1, const float* __restrict__ Wv)
{
    __shared__ __half th[32][130], tl[32][130];
    const int w  = blockIdx.x >> 2;            // 0: W1, 1: M, 2: Wv
    const int kc = blockIdx.x & 3;
    const float* W = (w == 0) ? W1 : (w == 1) ? g_M : Wv;
    const int Kw = (w == 0) ? IN_ : H_;
    for (int e = threadIdx.x; e < 32 * 128; e += 256) {
        int kg = e >> 7, n = e & 127;
        int kglob = kc * 32 + kg;
        float val = (kglob < Kw) ? W[kglob * H_ + n] : 0.f;
        __half hh = __float2half_rn(val);
        th[kg][n] = hh;
        tl[kg][n] = __float2half_rn(val - __half2float(hh));
    }
    __syncthreads();
    __half* dh = (__half*)&g_whl[w][0][kc][0];
    __half* dl = (__half*)&g_whl[w][1][kc][0];
    for (int e = threadIdx.x; e < 32 * 128; e += 256) {
        int k = e & 31, n = e >> 5;
        dh[e] = th[k][n];
        dl[e] = tl[k][n];
    }
}

// ---------------- main kernel ----------------
__global__ __launch_bounds__(NTHREADS, 2)
void exrest_fused_kernel(const float* __restrict__ x,  const float* __restrict__ b1,
                         const float* __restrict__ bv, const float* __restrict__ W2,
                         const float* __restrict__ b2, const float* __restrict__ W3,
                         const float* __restrict__ b3, const float* __restrict__ pe,
                         float* __restrict__ out, float* __restrict__ wout)
{
    extern __shared__ float sm[];
    __half* Ah = (__half*)sm;
    __half* Al = (__half*)(sm + AL_F);
    const __half2* Ah2 = (const __half2*)sm;
    const __half2* Al2 = (const __half2*)(sm + AL_F);
    float* smS = sm + SMS_F;                   // overlay on Ah rows 100..127
    float* sbv = sm + SBV_F;
    float* sb2 = sm + SB2_F;
    float* sW3 = sm + SW3_F;
    float* sb3 = sm + SB3_F;

    const int tid  = threadIdx.x;
    const int lane = tid & 31;
    const int wid  = tid >> 5;                 // 0..7
    const int g    = lane >> 2;
    const int cq   = lane & 3;
    const int nhalf = wid >> 2;                // 0..1: N 64-col half
    const int mrow  = (wid + 3 * nhalf) & 3;   // light (==3) warps at wid 3,4
    const bool fullM = (mrow < 3);
    const int bb   = blockIdx.x;

    const uint32_t sbase = smem_u32(sm);
    const uint32_t ALOFSB = AL_F * 4;
    const uint32_t WLOFSB = 10240;             // hi image bytes (128*80)

    // ---- stage consts + x (fp16 hi/lo, zero-padded 128x128) ----
    if (tid < H_)          sbv[tid] = bv[tid];
    if (tid < MID_)        sb2[tid] = b2[tid];
    if (tid < MID_ * OUT_) sW3[tid] = W3[tid];
    if (tid < OUT_)        sb3[tid] = b3[tid];
    {
        const float* xb = x + (long long)bb * (S_ * IN_);
        for (int e = tid; e < 128 * 64; e += NTHREADS) {
            int r = e >> 6, cp = (e & 63) * 2;
            float v0 = (r < S_ && cp     < IN_) ? xb[r * IN_ + cp]     : 0.f;
            float v1 = (r < S_ && cp + 1 < IN_) ? xb[r * IN_ + cp + 1] : 0.f;
            __half2 lo2;
            __half2 hi2 = split_hi2(v0, v1, lo2);
            *(__half2*)&Ah[r * SAH + cp] = hi2;
            *(__half2*)&Al[r * SAH + cp] = lo2;
        }
    }

    // ---- prologue: cp.async chunk 0 into buf 0 (4 x 16B per thread) ----
    {
        uint32_t base = sbase + WB_F * 4;
        #pragma unroll
        for (int i = 0; i < 4; i++) {
            int e = tid + 256 * i;
            int img = e >> 9, rem = e & 511;
            uint32_t d = base + (uint32_t)img * WLOFSB
                       + (uint32_t)(rem >> 2) * 80 + (uint32_t)(rem & 3) * 16;
            cp16(d, (const char*)&g_whl[0][img][0][0] + rem * 16);
        }
        cp_commit();
        cp_wait0();
    }
    __syncthreads();

    float c[2][8][4];
    #pragma unroll
    for (int mi = 0; mi < 2; mi++)
        #pragma unroll
        for (int nt = 0; nt < 8; nt++)
            #pragma unroll
            for (int rr = 0; rr < 4; rr++) c[mi][nt][rr] = 0.f;

    const float INV_SQRT_H = 0.08838834764831845f;

    const uint32_t aRowByte = (uint32_t)((mrow * 32 + (lane & 15)) * SAH
                                         + ((lane >> 4) << 3)) * 2;
    const int bq = lane >> 3;
    const uint32_t bRowHalf = (uint32_t)((nhalf * 64 + ((bq >> 1) << 3) + (lane & 7)) * SWH
                                         + ((bq & 1) << 3));

    for (int cc = 0; cc < 12; cc++) {
        const int p = cc & 1;
        if (cc < 11) {                         // cp.async next chunk -> other buf
            int nc = cc + 1;
            uint32_t base = sbase + WB_F * 4 + (uint32_t)(1 - p) * 20480;
            #pragma unroll
            for (int i = 0; i < 4; i++) {
                int e = tid + 256 * i;
                int img = e >> 9, rem = e & 511;
                uint32_t d = base + (uint32_t)img * WLOFSB
                           + (uint32_t)(rem >> 2) * 80 + (uint32_t)(rem & 3) * 16;
                cp16(d, (const char*)&g_whl[nc >> 2][img][nc & 3][0] + rem * 16);
            }
            cp_commit();
        }

        const int kc = cc & 3;
        const uint32_t wbase = sbase + (uint32_t)WB_F * 4 + (uint32_t)p * 20480;

        #pragma unroll
        for (int ks = 0; ks < 2; ks++) {
            const uint32_t aAddr = sbase + aRowByte + (uint32_t)(kc * 32 + ks * 16) * 2;
            uint32_t ah[2][4], al[2][4];
            ldm4(ah[0], aAddr);
            ldm4(al[0], aAddr + ALOFSB);
            if (fullM) {
                ldm4(ah[1], aAddr + 16 * SAH * 2);
                ldm4(al[1], aAddr + ALOFSB + 16 * SAH * 2);
            }

            #pragma unroll
            for (int gi = 0; gi < 4; gi++) {   // 2 nt per group
                const uint32_t bAddr = wbase
                    + (bRowHalf + (uint32_t)(gi * 16 * SWH) + (uint32_t)(ks * 16)) * 2;
                uint32_t r4[4], s4[4];
                ldm4(r4, bAddr);               // hi
                ldm4(s4, bAddr + WLOFSB);      // lo
                const int nt0 = gi * 2, nt1 = gi * 2 + 1;
                mma_f16(c[0][nt0], ah[0], r4[0], r4[1]);
                mma_f16(c[0][nt0], ah[0], s4[0], s4[1]);
                mma_f16(c[0][nt0], al[0], r4[0], r4[1]);
                mma_f16(c[0][nt1], ah[0], r4[2], r4[3]);
                mma_f16(c[0][nt1], ah[0], s4[2], s4[3]);
                mma_f16(c[0][nt1], al[0], r4[2], r4[3]);
                if (fullM) {
                    mma_f16(c[1][nt0], ah[1], r4[0], r4[1]);
                    mma_f16(c[1][nt0], ah[1], s4[0], s4[1]);
                    mma_f16(c[1][nt0], al[1], r4[0], r4[1]);
                    mma_f16(c[1][nt1], ah[1], r4[2], r4[3]);
                    mma_f16(c[1][nt1], ah[1], s4[2], s4[3]);
                    mma_f16(c[1][nt1], al[1], r4[2], r4[3]);
                }
            }
        }

        if ((cc & 3) == 3) {
            const int gm = cc >> 2;            // 0: h   1: t (scores)   2: v

            if (gm == 0) {
                __syncthreads();               // all ldmatrix reads of A done
                #pragma unroll
                for (int mi = 0; mi < 2; mi++)
                    #pragma unroll
                    for (int hi = 0; hi < 2; hi++) {
                        int r = mrow * 32 + mi * 16 + hi * 8 + g;
                        if (r < S_) {
                            #pragma unroll
                            for (int nt = 0; nt < 8; nt++) {
                                int col = nhalf * 64 + nt * 8 + 2 * cq;
                                float v0 = c[mi][nt][hi * 2 + 0] + b1[col];
                                float v1 = c[mi][nt][hi * 2 + 1] + b1[col + 1];
                                v0 = fmaxf(v0, 0.f) + pe[r * H_ + col];
                                v1 = fmaxf(v1, 0.f) + pe[r * H_ + col + 1];
                                __half2 lo2;
                                __half2 hi2 = split_hi2(v0, v1, lo2);
                                *(__half2*)&Ah[r * SAH + col] = hi2;
                                *(__half2*)&Al[r * SAH + col] = lo2;
                            }
                        }
                    }
            } else if (gm == 1) {
                // t fragments -> banded scores vs h (per 64-col half)
                #pragma unroll
                for (int mi = 0; mi < 2; mi++)
                    #pragma unroll
                    for (int hi = 0; hi < 2; hi++) {
                        int r = mrow * 32 + mi * 16 + hi * 8 + g;
                        #pragma unroll
                        for (int m = 0; m < 5; m++) {
                            int j = r + 2 - m;
                            float pf = 0.f;
                            if (r < S_ && j >= 0 && j < S_) {
                                #pragma unroll
                                for (int nt = 0; nt < 8; nt++) {
                                    int cw = nhalf * 32 + nt * 4 + cq;
                                    float2 a2 = __half22float2(Ah2[j * 68 + cw]);
                                    float2 l2 = __half22float2(Al2[j * 68 + cw]);
                                    pf = fmaf(c[mi][nt][hi * 2 + 0], a2.x + l2.x, pf);
                                    pf = fmaf(c[mi][nt][hi * 2 + 1], a2.y + l2.y, pf);
                                }
                            }
                            pf += __shfl_xor_sync(0xffffffffu, pf, 1);
                            pf += __shfl_xor_sync(0xffffffffu, pf, 2);
                            if (cq == 0 && r < S_)
                                smS[nhalf * 800 + r * 8 + m] = pf;
                        }
                    }
                __syncthreads();
                if (tid < S_) {
                    int s = tid;
                    float sc[5];
                    #pragma unroll
                    for (int m = 0; m < 5; m++)
                        sc[m] = (smS[s * 8 + m] + smS[800 + s * 8 + m]) * INV_SQRT_H;
                    float mx = sc[0];
                    #pragma unroll
                    for (int m = 1; m < 5; m++) mx = fmaxf(mx, sc[m]);
                    float e5[5], sum = 0.f;
                    #pragma unroll
                    for (int m = 0; m < 5; m++) { e5[m] = __expf(sc[m] - mx); sum += e5[m]; }
                    float rs = 1.f / sum;
                    float* wp = wout + ((long long)bb * S_ + s) * 5;
                    #pragma unroll
                    for (int m = 0; m < 5; m++) {
                        float wmm = e5[m] * rs;
                        wp[m] = wmm;
                        smS[s * 8 + m] = wmm;
                    }
                }
            } else {
                __syncthreads();               // all chunk-11 reads of A done
                #pragma unroll
                for (int mi = 0; mi < 2; mi++)
                    #pragma unroll
                    for (int hi = 0; hi < 2; hi++) {
                        int r = mrow * 32 + mi * 16 + hi * 8 + g;
                        if (r < S_) {
                            #pragma unroll
                            for (int nt = 0; nt < 8; nt++) {
                                int col = nhalf * 64 + nt * 8 + 2 * cq;
                                float v0 = c[mi][nt][hi * 2 + 0] + sbv[col];
                                float v1 = c[mi][nt][hi * 2 + 1] + sbv[col + 1];
                                __half2 lo2;
                                __half2 hi2 = split_hi2(v0, v1, lo2);
                                *(__half2*)&Ah[r * SAH + col] = hi2;
                                *(__half2*)&Al[r * SAH + col] = lo2;
                            }
                        }
                    }
            }

            if (gm < 2) {
                #pragma unroll
                for (int mi = 0; mi < 2; mi++)
                    #pragma unroll
                    for (int nt = 0; nt < 8; nt++)
                        #pragma unroll
                        for (int rr = 0; rr < 4; rr++) c[mi][nt][rr] = 0.f;
            }
        }

        cp_wait0();
        __syncthreads();                       // next buf ready + A writes visible
    }

    // ---- Phase 3: context + FFN (2 tokens / warp / iter) ----
    float* sctx = sm + WB_F;                         // 16 x 128 = 2048 fl
    float2* w2f2 = (float2*)(sm + WB_F + 2048);      // 4096 fl
    const u64* wbu = (const u64*)(sm + WB_F + 2048);
    for (int e = tid; e < 64 * MID_; e += NTHREADS) {
        int kp = e >> 5, col = e & 31;
        float2 wv;
        wv.x = W2[(2 * kp    ) * MID_ + col];
        wv.y = W2[(2 * kp + 1) * MID_ + col];
        w2f2[e] = wv;
    }
    __syncthreads();

    const float w3a = sW3[lane * 2 + 0];
    const float w3b = sW3[lane * 2 + 1];
    const float b2l = sb2[lane];
    const float b30 = sb3[0], b31 = sb3[1];
    const float bva0 = sbv[lane * 4], bva1 = sbv[lane * 4 + 1];
    const float bvb0 = sbv[lane * 4 + 2], bvb1 = sbv[lane * 4 + 3];

    for (int sbt = wid * 2; sbt < S_; sbt += 16) {
        #pragma unroll
        for (int t = 0; t < 2; t++) {
            int s = sbt + t;
            u64 c0 = 0ull, c1 = 0ull;
            #pragma unroll
            for (int m = 0; m < 5; m++) {
                int j = s + 2 - m;
                float wm = smS[s * 8 + m];
                u64 wmp = pk(wm, wm);
                float2 va, vb2;
                if (j >= 0 && j < S_) {
                    int idx = j * 68 + lane * 2;
                    float2 a0 = __half22float2(Ah2[idx]);
                    float2 l0 = __half22float2(Al2[idx]);
                    float2 a1 = __half22float2(Ah2[idx + 1]);
                    float2 l1 = __half22float2(Al2[idx + 1]);
                    va.x = a0.x + l0.x; va.y = a0.y + l0.y;
                    vb2.x = a1.x + l1.x; vb2.y = a1.y + l1.y;
                } else {
                    va.x = bva0; va.y = bva1;
                    vb2.x = bvb0; vb2.y = bvb1;
                }
                fma2(c0, wmp, pk(va.x, va.y));
                fma2(c1, wmp, pk(vb2.x, vb2.y));
            }
            u64* cd = (u64*)(sctx + (wid * 2 + t) * H_ + lane * 4);
            cd[0] = c0;
            cd[1] = c1;
        }
        __syncwarp();

        const u64* c0u = (const u64*)(sctx + (wid * 2) * H_);
        const u64* c1u = c0u + 64;
        u64 m0 = 0ull, m1 = 0ull;
        #pragma unroll
        for (int kp = 0; kp < 64; kp += 2) {
            u64 w0 = wbu[ kp      * MID_ + lane];
            u64 w1 = wbu[(kp + 1) * MID_ + lane];
            fma2(m0, c0u[kp],     w0);
            fma2(m0, c0u[kp + 1], w1);
            fma2(m1, c1u[kp],     w0);
            fma2(m1, c1u[kp + 1], w1);
        }

        #pragma unroll
        for (int t = 0; t < 2; t++) {
            int s = sbt + t;
            float2 mm = up(t ? m1 : m0);
            float mid = fmaxf(mm.x + mm.y + b2l, 0.f);
            float p0 = mid * w3a;
            float p1 = mid * w3b;
            #pragma unroll
            for (int off = 16; off > 0; off >>= 1) {
                p0 += __shfl_xor_sync(0xffffffffu, p0, off);
                p1 += __shfl_xor_sync(0xffffffffu, p1, off);
            }
            if (lane == 0) {
                float* op = out + ((long long)bb * S_ + s) * 2;
                op[0] = p0 + b30;
                op[1] = p1 + b31;
            }
        }
        __syncwarp();
    }
}

extern "C" void kernel_launch(void* const* d_in, const int* in_sizes, int n_in,
                              void* d_out, int out_size)
{
    const float* x  = (const float*)d_in[0];
    const float* W1 = (const float*)d_in[1];
    const float* b1 = (const float*)d_in[2];
    const float* Wq = (const float*)d_in[3];
    const float* Wk = (const float*)d_in[4];
    const float* Wv = (const float*)d_in[5];
    const float* bv = (const float*)d_in[6];
    const float* W2 = (const float*)d_in[7];
    const float* b2 = (const float*)d_in[8];
    const float* W3 = (const float*)d_in[9];
    const float* b3 = (const float*)d_in[10];
    const float* pe = (const float*)d_in[11];

    float* out  = (float*)d_out;                    // (B,S,2)
    float* wout = out + (long long)B_ * S_ * OUT_;  // (B,S,1,5)

    cudaFuncSetAttribute(exrest_fused_kernel,
                         cudaFuncAttributeMaxDynamicSharedMemorySize, SMEM_BYTES);

    prep_M<<<64, 256>>>(Wq, Wk);
    prep_weights<<<12, 256>>>(W1, Wv);
    exrest_fused_kernel<<<B_, NTHREADS, SMEM_BYTES>>>(
        x, b1, bv, W2, b2, W3, b3, pe, out, wout);
}

// round 14
// speedup vs baseline: 3.4628x; 1.5936x over previous
#include <cuda_runtime.h>
#include <cuda_fp16.h>
#include <cstdint>

// ExRestSelfAtten, round 12: fold Wv@W2 -> p-GEMM with N=32 (25% less MMA),
// phase 3 collapses to banded avg over 32 cols; fused single prep kernel;
// skip all-zero ks of h-GEMM chunk 3. 2 CTAs/SM, fp16 split hi/lo 3-chain.

#define B_    1024
#define S_    100
#define IN_   100
#define H_    128
#define MID_  32
#define OUT_  2
#define NTHREADS 256

#define SAH 136   // A row stride (halves)
#define SWH 40    // W-stage row stride (halves)

// SMEM float offsets
#define AH_F   0        // Ah 128x136 halves; rows 100-127 tail = smS overlay
#define AL_F   8704
#define WB_F   17408    // 2 staging buffers x 5120 fl; afterwards: p buffer
#define SB2_F  27776    // cb2 (32 fl)
#define SW3_F  27808
#define SB3_F  27872
#define SMEM_FLOATS 27874
#define SMEM_BYTES  (SMEM_FLOATS * 4)

#define SMS_F  6800     // smS overlay on Ah rows 100..127: [2][100][8]

typedef unsigned long long u64;

__device__ uint4 g_whl[2][2][4][512];          // [w: W1,M][hi/lo][kc][n128xk32]
__device__ uint4 g_wv2[2][4][128];             // [hi/lo][kc][c32xk32]
__device__ float g_cb2[MID_];

// ---------------- helpers ----------------
__device__ __forceinline__ uint32_t smem_u32(const void* p) {
    uint32_t a;
    asm("{ .reg .u64 t; cvta.to.shared.u64 t, %1; cvt.u32.u64 %0, t; }" : "=r"(a) : "l"(p));
    return a;
}
__device__ __forceinline__ void mma_f16(float* c, const uint32_t* a,
                                        uint32_t b0, uint32_t b1) {
    asm volatile(
        "mma.sync.aligned.m16n8k16.row.col.f32.f16.f16.f32 "
        "{%0,%1,%2,%3}, {%4,%5,%6,%7}, {%8,%9}, {%0,%1,%2,%3};"
        : "+f"(c[0]), "+f"(c[1]), "+f"(c[2]), "+f"(c[3])
        : "r"(a[0]), "r"(a[1]), "r"(a[2]), "r"(a[3]), "r"(b0), "r"(b1));
}
__device__ __forceinline__ void ldm4(uint32_t* r, uint32_t addr) {
    asm volatile("ldmatrix.sync.aligned.m8n8.x4.shared.b16 {%0,%1,%2,%3}, [%4];"
                 : "=r"(r[0]), "=r"(r[1]), "=r"(r[2]), "=r"(r[3]) : "r"(addr));
}
__device__ __forceinline__ void cp16(uint32_t dst, const void* src) {
    asm volatile("cp.async.ca.shared.global [%0], [%1], 16;" :: "r"(dst), "l"(src) : "memory");
}
__device__ __forceinline__ void cp_commit() {
    asm volatile("cp.async.commit_group;" ::: "memory");
}
__device__ __forceinline__ void cp_wait0() {
    asm volatile("cp.async.wait_group 0;" ::: "memory");
}
__device__ __forceinline__ __half2 split_hi2(float v0, float v1, __half2& lo2) {
    __half h0 = __float2half_rn(v0), h1 = __float2half_rn(v1);
    lo2 = __halves2half2(__float2half_rn(v0 - __half2float(h0)),
                         __float2half_rn(v1 - __half2float(h1)));
    return __halves2half2(h0, h1);
}

// ---------------- fused prep: 13 blocks ----------------
// 0-3: W1 chunks -> g_whl[0]; 4-7: M=Wq@Wk^T chunks -> g_whl[1];
// 8-11: W_v2=Wv@W2 chunks -> g_wv2; 12: cb2 = b2 + bv@W2.
__global__ void prep_all(const float* __restrict__ W1, const float* __restrict__ Wq,
                         const float* __restrict__ Wk, const float* __restrict__ Wv,
                         const float* __restrict__ W2, const float* __restrict__ bv,
                         const float* __restrict__ b2)
{
    __shared__ float sbuf[32 * 129 + 32 * 128];
    const int bid = blockIdx.x, tid = threadIdx.x;

    if (bid < 8) {
        float* tile = sbuf;                    // [32 k][129] fp32
        const int w = bid >> 2, kc = bid & 3;
        if (w == 0) {
            for (int e = tid; e < 4096; e += 256) {
                int kg = e >> 7, n = e & 127;
                int kglob = kc * 32 + kg;
                tile[kg * 129 + n] = (kglob < IN_) ? W1[kglob * H_ + n] : 0.f;
            }
            __syncthreads();
        } else {
            float* sWq = sbuf + 32 * 129;
            const int a0 = kc * 32;
            for (int e = tid; e < 4096; e += 256)
                sWq[e] = Wq[(a0 + (e >> 7)) * H_ + (e & 127)];
            __syncthreads();
            const int n = tid & 127, half = tid >> 7;
            float acc[16];
            #pragma unroll
            for (int t = 0; t < 16; t++) acc[t] = 0.f;
            const float4* wkn = (const float4*)(Wk + n * H_);
            for (int i = 0; i < 32; i++) {
                float4 kv = wkn[i];
                #pragma unroll
                for (int t = 0; t < 16; t++) {
                    const float* q = sWq + (half * 16 + t) * 128 + i * 4;
                    acc[t] = fmaf(q[0], kv.x, fmaf(q[1], kv.y,
                              fmaf(q[2], kv.z, fmaf(q[3], kv.w, acc[t]))));
                }
            }
            #pragma unroll
            for (int t = 0; t < 16; t++) tile[(half * 16 + t) * 129 + n] = acc[t];
            __syncthreads();
        }
        __half* dh = (__half*)&g_whl[w][0][kc][0];
        __half* dl = (__half*)&g_whl[w][1][kc][0];
        for (int e = tid; e < 4096; e += 256) {   // e = n*32 + k
            int k = e & 31, n = e >> 5;
            float val = tile[k * 129 + n];
            __half hh = __float2half_rn(val);
            dh[e] = hh;
            dl[e] = __float2half_rn(val - __half2float(hh));
        }
    } else if (bid < 12) {
        const int kc = bid - 8;
        float* sW2s = sbuf;                    // [128 n][32 c]
        float* sWv  = sbuf + 4096;             // [32 k][128 n]
        for (int e = tid; e < 4096; e += 256) {
            sW2s[e] = W2[e];
            sWv[e]  = Wv[(kc * 32 + (e >> 7)) * H_ + (e & 127)];
        }
        __syncthreads();
        __half* dh = (__half*)&g_wv2[0][kc][0];
        __half* dl = (__half*)&g_wv2[1][kc][0];
        #pragma unroll
        for (int i = 0; i < 4; i++) {
            int o = tid + 256 * i;             // k = o>>5, c = o&31
            int k = o >> 5, cc = o & 31;
            float acc = 0.f;
            #pragma unroll 8
            for (int n = 0; n < 128; n++)
                acc = fmaf(sWv[k * 128 + n], sW2s[n * 32 + cc], acc);
            int e = cc * 32 + k;               // [c][k] layout
            __half hh = __float2half_rn(acc);
            dh[e] = hh;
            dl[e] = __float2half_rn(acc - __half2float(hh));
        }
    } else {
        if (tid < MID_) {
            float acc = b2[tid];
            for (int n = 0; n < 128; n++)
                acc = fmaf(bv[n], W2[n * 32 + tid], acc);
            g_cb2[tid] = acc;
        }
    }
}

// ---------------- main kernel ----------------
__global__ __launch_bounds__(NTHREADS, 2)
void exrest_fused_kernel(const float* __restrict__ x,  const float* __restrict__ b1,
                         const float* __restrict__ W3, const float* __restrict__ b3,
                         const float* __restrict__ pe,
                         float* __restrict__ out, float* __restrict__ wout)
{
    extern __shared__ float sm[];
    __half* Ah = (__half*)sm;
    __half* Al = (__half*)(sm + AL_F);
    const __half2* Ah2 = (const __half2*)sm;
    const __half2* Al2 = (const __half2*)(sm + AL_F);
    float* smS  = sm + SMS_F;                  // overlay on Ah rows 100..127
    float* cb2s = sm + SB2_F;
    float* sW3  = sm + SW3_F;
    float* sb3  = sm + SB3_F;

    const int tid  = threadIdx.x;
    const int lane = tid & 31;
    const int wid  = tid >> 5;                 // 0..7
    const int g    = lane >> 2;
    const int cq   = lane & 3;
    const int nhalf = wid >> 2;                // chunks 0-7: N 64-col half
    const int mrow  = (wid + 3 * nhalf) & 3;   // light (==3) warps spread
    const bool fullM = (mrow < 3);
    const int bb   = blockIdx.x;

    const uint32_t sbase = smem_u32(sm);
    const uint32_t ALOFSB = AL_F * 4;
    const uint32_t WLOFSB = 10240;             // hi image bytes in stage buf

    if (tid < MID_)        cb2s[tid] = g_cb2[tid];
    if (tid < MID_ * OUT_) sW3[tid] = W3[tid];
    if (tid < OUT_)        sb3[tid] = b3[tid];
    {
        const float* xb = x + (long long)bb * (S_ * IN_);
        for (int e = tid; e < 128 * 64; e += NTHREADS) {
            int r = e >> 6, cp = (e & 63) * 2;
            float v0 = (r < S_ && cp     < IN_) ? xb[r * IN_ + cp]     : 0.f;
            float v1 = (r < S_ && cp + 1 < IN_) ? xb[r * IN_ + cp + 1] : 0.f;
            __half2 lo2;
            __half2 hi2 = split_hi2(v0, v1, lo2);
            *(__half2*)&Ah[r * SAH + cp] = hi2;
            *(__half2*)&Al[r * SAH + cp] = lo2;
        }
    }

    // staging: chunk nc -> buffer base (byte addr)
    auto stage_chunk = [&](uint32_t base, int nc) {
        if (nc < 8) {
            #pragma unroll
            for (int i = 0; i < 4; i++) {
                int e = tid + 256 * i;
                int img = e >> 9, rem = e & 511;
                uint32_t d = base + (uint32_t)img * WLOFSB
                           + (uint32_t)(rem >> 2) * 80 + (uint32_t)(rem & 3) * 16;
                cp16(d, (const char*)&g_whl[nc >> 2][img][nc & 3][0] + rem * 16);
            }
        } else {
            int img = tid >> 7, rem = tid & 127;
            uint32_t d = base + (uint32_t)img * WLOFSB
                       + (uint32_t)(rem >> 2) * 80 + (uint32_t)(rem & 3) * 16;
            cp16(d, (const char*)&g_wv2[img][nc - 8][0] + rem * 16);
        }
    };

    stage_chunk(sbase + WB_F * 4, 0);
    cp_commit();
    cp_wait0();
    __syncthreads();

    float c[2][8][4];
    #pragma unroll
    for (int mi = 0; mi < 2; mi++)
        #pragma unroll
        for (int nt = 0; nt < 8; nt++)
            #pragma unroll
            for (int rr = 0; rr < 4; rr++) c[mi][nt][rr] = 0.f;

    const float INV_SQRT_H = 0.08838834764831845f;

    const uint32_t aRowByte = (uint32_t)((mrow * 32 + (lane & 15)) * SAH
                                         + ((lane >> 4) << 3)) * 2;
    const uint32_t aRowByteP = (uint32_t)((wid * 16 + (lane & 15)) * SAH
                                          + ((lane >> 4) << 3)) * 2;
    const int bq = lane >> 3;
    const uint32_t bRowHalf = (uint32_t)((nhalf * 64 + ((bq >> 1) << 3) + (lane & 7)) * SWH
                                         + ((bq & 1) << 3));
    const uint32_t bRowHalfP = (uint32_t)((((bq >> 1) << 3) + (lane & 7)) * SWH
                                          + ((bq & 1) << 3));

    for (int cc = 0; cc < 12; cc++) {
        const int p = cc & 1;
        if (cc < 11) {
            stage_chunk(sbase + WB_F * 4 + (uint32_t)(1 - p) * 20480, cc + 1);
            cp_commit();
        }
        const uint32_t wbase = sbase + (uint32_t)WB_F * 4 + (uint32_t)p * 20480;

        if (cc < 8) {
            const int kc = cc & 3;
            #pragma unroll
            for (int ks = 0; ks < 2; ks++) {
                if (cc == 3 && ks == 1) continue;   // x cols 112-127 are zero
                const uint32_t aAddr = sbase + aRowByte + (uint32_t)(kc * 32 + ks * 16) * 2;
                uint32_t ah[2][4], al[2][4];
                ldm4(ah[0], aAddr);
                ldm4(al[0], aAddr + ALOFSB);
                if (fullM) {
                    ldm4(ah[1], aAddr + 16 * SAH * 2);
                    ldm4(al[1], aAddr + ALOFSB + 16 * SAH * 2);
                }
                #pragma unroll
                for (int gi = 0; gi < 4; gi++) {
                    const uint32_t bAddr = wbase
                        + (bRowHalf + (uint32_t)(gi * 16 * SWH) + (uint32_t)(ks * 16)) * 2;
                    uint32_t r4[4], s4[4];
                    ldm4(r4, bAddr);
                    ldm4(s4, bAddr + WLOFSB);
                    const int nt0 = gi * 2, nt1 = gi * 2 + 1;
                    mma_f16(c[0][nt0], ah[0], r4[0], r4[1]);
                    mma_f16(c[0][nt0], ah[0], s4[0], s4[1]);
                    mma_f16(c[0][nt0], al[0], r4[0], r4[1]);
                    mma_f16(c[0][nt1], ah[0], r4[2], r4[3]);
                    mma_f16(c[0][nt1], ah[0], s4[2], s4[3]);
                    mma_f16(c[0][nt1], al[0], r4[2], r4[3]);
                    if (fullM) {
                        mma_f16(c[1][nt0], ah[1], r4[0], r4[1]);
                        mma_f16(c[1][nt0], ah[1], s4[0], s4[1]);
                        mma_f16(c[1][nt0], al[1], r4[0], r4[1]);
                        mma_f16(c[1][nt1], ah[1], r4[2], r4[3]);
                        mma_f16(c[1][nt1], ah[1], s4[2], s4[3]);
                        mma_f16(c[1][nt1], al[1], r4[2], r4[3]);
                    }
                }
            }
        } else if (wid < 7) {                  // p = h @ W_v2 (N=32)
            const int kcp = cc - 8;
            #pragma unroll
            for (int ks = 0; ks < 2; ks++) {
                const uint32_t aAddr = sbase + aRowByteP + (uint32_t)(kcp * 32 + ks * 16) * 2;
                uint32_t ah[4], al[4];
                ldm4(ah, aAddr);
                ldm4(al, aAddr + ALOFSB);
                #pragma unroll
                for (int gi = 0; gi < 2; gi++) {
                    const uint32_t bAddr = wbase
                        + (bRowHalfP + (uint32_t)(gi * 16 * SWH) + (uint32_t)(ks * 16)) * 2;
                    uint32_t r4[4], s4[4];
                    ldm4(r4, bAddr);
                    ldm4(s4, bAddr + WLOFSB);
                    const int nt0 = gi * 2, nt1 = gi * 2 + 1;
                    mma_f16(c[0][nt0], ah, r4[0], r4[1]);
                    mma_f16(c[0][nt0], ah, s4[0], s4[1]);
                    mma_f16(c[0][nt0], al, r4[0], r4[1]);
                    mma_f16(c[0][nt1], ah, r4[2], r4[3]);
                    mma_f16(c[0][nt1], ah, s4[2], s4[3]);
                    mma_f16(c[0][nt1], al, r4[2], r4[3]);
                }
            }
        }

        if (cc == 3) {
            __syncthreads();                   // all ldmatrix reads of A done
            #pragma unroll
            for (int mi = 0; mi < 2; mi++)
                #pragma unroll
                for (int hi = 0; hi < 2; hi++) {
                    int r = mrow * 32 + mi * 16 + hi * 8 + g;
                    if (r < S_) {
                        #pragma unroll
                        for (int nt = 0; nt < 8; nt++) {
                            int col = nhalf * 64 + nt * 8 + 2 * cq;
                            float v0 = c[mi][nt][hi * 2 + 0] + b1[col];
                            float v1 = c[mi][nt][hi * 2 + 1] + b1[col + 1];
                            v0 = fmaxf(v0, 0.f) + pe[r * H_ + col];
                            v1 = fmaxf(v1, 0.f) + pe[r * H_ + col + 1];
                            __half2 lo2;
                            __half2 hi2 = split_hi2(v0, v1, lo2);
                            *(__half2*)&Ah[r * SAH + col] = hi2;
                            *(__half2*)&Al[r * SAH + col] = lo2;
                        }
                    }
                }
            #pragma unroll
            for (int mi = 0; mi < 2; mi++)
                #pragma unroll
                for (int nt = 0; nt < 8; nt++)
                    #pragma unroll
                    for (int rr = 0; rr < 4; rr++) c[mi][nt][rr] = 0.f;
        } else if (cc == 7) {
            // t fragments -> banded scores vs h
            #pragma unroll
            for (int mi = 0; mi < 2; mi++)
                #pragma unroll
                for (int hi = 0; hi < 2; hi++) {
                    int r = mrow * 32 + mi * 16 + hi * 8 + g;
                    #pragma unroll
                    for (int m = 0; m < 5; m++) {
                        int j = r + 2 - m;
                        float pf = 0.f;
                        if (r < S_ && j >= 0 && j < S_) {
                            #pragma unroll
                            for (int nt = 0; nt < 8; nt++) {
                                int cw = nhalf * 32 + nt * 4 + cq;
                                float2 a2 = __half22float2(Ah2[j * 68 + cw]);
                                float2 l2 = __half22float2(Al2[j * 68 + cw]);
                                pf = fmaf(c[mi][nt][hi * 2 + 0], a2.x + l2.x, pf);
                                pf = fmaf(c[mi][nt][hi * 2 + 1], a2.y + l2.y, pf);
                            }
                        }
                        pf += __shfl_xor_sync(0xffffffffu, pf, 1);
                        pf += __shfl_xor_sync(0xffffffffu, pf, 2);
                        if (cq == 0 && r < S_)
                            smS[nhalf * 800 + r * 8 + m] = pf;
                    }
                }
            __syncthreads();
            if (tid < S_) {
                int s = tid;
                float sc[5];
                #pragma unroll
                for (int m = 0; m < 5; m++)
                    sc[m] = (smS[s * 8 + m] + smS[800 + s * 8 + m]) * INV_SQRT_H;
                float mx = sc[0];
                #pragma unroll
                for (int m = 1; m < 5; m++) mx = fmaxf(mx, sc[m]);
                float e5[5], sum = 0.f;
                #pragma unroll
                for (int m = 0; m < 5; m++) { e5[m] = __expf(sc[m] - mx); sum += e5[m]; }
                float rs = 1.f / sum;
                float* wp = wout + ((long long)bb * S_ + s) * 5;
                #pragma unroll
                for (int m = 0; m < 5; m++) {
                    float wmm = e5[m] * rs;
                    wp[m] = wmm;
                    smS[s * 8 + m] = wmm;
                }
            }
            #pragma unroll
            for (int mi = 0; mi < 2; mi++)
                #pragma unroll
                for (int nt = 0; nt < 8; nt++)
                    #pragma unroll
                    for (int rr = 0; rr < 4; rr++) c[mi][nt][rr] = 0.f;
        }

        cp_wait0();
        __syncthreads();
    }

    // ---- p epilogue: write p fp32 into (now free) staging region ----
    float* pbuf = sm + WB_F;                   // [100][stride 33]
    if (wid < 7) {
        #pragma unroll
        for (int hi = 0; hi < 2; hi++) {
            int r = wid * 16 + hi * 8 + g;
            if (r < S_) {
                #pragma unroll
                for (int nt = 0; nt < 4; nt++) {
                    int col = nt * 8 + 2 * cq;
                    pbuf[r * 33 + col]     = c[0][nt][hi * 2 + 0];
                    pbuf[r * 33 + col + 1] = c[0][nt][hi * 2 + 1];
                }
            }
        }
    }
    __syncthreads();

    // ---- final: mid = relu(banded avg of p + cb2); out = mid @ W3 + b3 ----
    const float w3a = sW3[lane * 2 + 0];
    const float w3b = sW3[lane * 2 + 1];
    const float cb2l = cb2s[lane];
    const float b30 = sb3[0], b31 = sb3[1];

    for (int s = wid; s < S_; s += 8) {
        float mid = cb2l;
        #pragma unroll
        for (int m = 0; m < 5; m++) {
            int j = s + 2 - m;
            if (j >= 0 && j < S_)
                mid = fmaf(smS[s * 8 + m], pbuf[j * 33 + lane], mid);
        }
        mid = fmaxf(mid, 0.f);
        float p0 = mid * w3a;
        float p1 = mid * w3b;
        #pragma unroll
        for (int off = 16; off > 0; off >>= 1) {
            p0 += __shfl_xor_sync(0xffffffffu, p0, off);
            p1 += __shfl_xor_sync(0xffffffffu, p1, off);
        }
        if (lane == 0) {
            float* op = out + ((long long)bb * S_ + s) * 2;
            op[0] = p0 + b30;
            op[1] = p1 + b31;
        }
    }
}

extern "C" void kernel_launch(void* const* d_in, const int* in_sizes, int n_in,
                              void* d_out, int out_size)
{
    const float* x  = (const float*)d_in[0];
    const float* W1 = (const float*)d_in[1];
    const float* b1 = (const float*)d_in[2];
    const float* Wq = (const float*)d_in[3];
    const float* Wk = (const float*)d_in[4];
    const float* Wv = (const float*)d_in[5];
    const float* bv = (const float*)d_in[6];
    const float* W2 = (const float*)d_in[7];
    const float* b2 = (const float*)d_in[8];
    const float* W3 = (const float*)d_in[9];
    const float* b3 = (const float*)d_in[10];
    const float* pe = (const float*)d_in[11];

    float* out  = (float*)d_out;                    // (B,S,2)
    float* wout = out + (long long)B_ * S_ * OUT_;  // (B,S,1,5)

    cudaFuncSetAttribute(exrest_fused_kernel,
                         cudaFuncAttributeMaxDynamicSharedMemorySize, SMEM_BYTES);

    prep_all<<<13, 256>>>(W1, Wq, Wk, Wv, W2, bv, b2);
    exrest_fused_kernel<<<B_, NTHREADS, SMEM_BYTES>>>(
        x, b1, W3, b3, pe, out, wout);
}

// round 15
// speedup vs baseline: 3.7109x; 1.0716x over previous
#include <cuda_runtime.h>
#include <cuda_fp16.h>
#include <cstdint>

// ExRestSelfAtten, round 15: r12 + p-GEMM merged to 2 chunks (wv2 staged in
// pairs), prep parallelized to 17 blocks, float2 x/b1/pe traffic.
// 3 GEMMs (h, t=h@M, p=h@(Wv@W2)), fp16 split hi/lo 3-chain m16n8k16.
// 2 CTAs/SM, 256 threads, banded scores from t fragments vs h.

#define B_    1024
#define S_    100
#define IN_   100
#define H_    128
#define MID_  32
#define OUT_  2
#define NTHREADS 256

#define SAH 136   // A row stride (halves)
#define SWH 40    // W-stage row stride (halves)

// SMEM float offsets
#define AH_F   0        // Ah 128x136 halves; rows 100-127 tail = smS overlay
#define AL_F   8704
#define WB_F   17408    // 2 staging buffers x 5120 fl; afterwards: p buffer
#define SB2_F  27776    // cb2 (32 fl)
#define SW3_F  27808
#define SB3_F  27872
#define SMEM_FLOATS 27874
#define SMEM_BYTES  (SMEM_FLOATS * 4)

#define SMS_F  6800     // smS overlay on Ah rows 100..127: [2][100][8]

typedef unsigned long long u64;

__device__ uint4 g_whl[2][2][4][512];          // [w: W1,M][hi/lo][kc][n128xk32]
__device__ uint4 g_wv2[2][4][128];             // [hi/lo][kc][c32xk32]
__device__ float g_cb2[MID_];

// ---------------- helpers ----------------
__device__ __forceinline__ uint32_t smem_u32(const void* p) {
    uint32_t a;
    asm("{ .reg .u64 t; cvta.to.shared.u64 t, %1; cvt.u32.u64 %0, t; }" : "=r"(a) : "l"(p));
    return a;
}
__device__ __forceinline__ void mma_f16(float* c, const uint32_t* a,
                                        uint32_t b0, uint32_t b1) {
    asm volatile(
        "mma.sync.aligned.m16n8k16.row.col.f32.f16.f16.f32 "
        "{%0,%1,%2,%3}, {%4,%5,%6,%7}, {%8,%9}, {%0,%1,%2,%3};"
        : "+f"(c[0]), "+f"(c[1]), "+f"(c[2]), "+f"(c[3])
        : "r"(a[0]), "r"(a[1]), "r"(a[2]), "r"(a[3]), "r"(b0), "r"(b1));
}
__device__ __forceinline__ void ldm4(uint32_t* r, uint32_t addr) {
    asm volatile("ldmatrix.sync.aligned.m8n8.x4.shared.b16 {%0,%1,%2,%3}, [%4];"
                 : "=r"(r[0]), "=r"(r[1]), "=r"(r[2]), "=r"(r[3]) : "r"(addr));
}
__device__ __forceinline__ void cp16(uint32_t dst, const void* src) {
    asm volatile("cp.async.ca.shared.global [%0], [%1], 16;" :: "r"(dst), "l"(src) : "memory");
}
__device__ __forceinline__ void cp_commit() {
    asm volatile("cp.async.commit_group;" ::: "memory");
}
__device__ __forceinline__ void cp_wait0() {
    asm volatile("cp.async.wait_group 0;" ::: "memory");
}
__device__ __forceinline__ __half2 split_hi2(float v0, float v1, __half2& lo2) {
    __half h0 = __float2half_rn(v0), h1 = __float2half_rn(v1);
    lo2 = __halves2half2(__float2half_rn(v0 - __half2float(h0)),
                         __float2half_rn(v1 - __half2float(h1)));
    return __halves2half2(h0, h1);
}

// ---------------- fused prep: 17 blocks ----------------
// 0-3: W1 chunks; 4-11: M=Wq@Wk^T half-chunks (16 rows each); 12-15: Wv@W2
// chunks; 16: cb2 = b2 + bv@W2.
__global__ void prep_all(const float* __restrict__ W1, const float* __restrict__ Wq,
                         const float* __restrict__ Wk, const float* __restrict__ Wv,
                         const float* __restrict__ W2, const float* __restrict__ bv,
                         const float* __restrict__ b2)
{
    __shared__ float sbuf[32 * 129];
    const int bid = blockIdx.x, tid = threadIdx.x;

    if (bid < 4) {
        // W1 chunk kc=bid: load [32 k][128 n] fp32, transpose-convert
        float* tile = sbuf;                    // [32 k][129]
        const int kc = bid;
        for (int e = tid; e < 4096; e += 256) {
            int kg = e >> 7, n = e & 127;
            int kglob = kc * 32 + kg;
            tile[kg * 129 + n] = (kglob < IN_) ? W1[kglob * H_ + n] : 0.f;
        }
        __syncthreads();
        __half* dh = (__half*)&g_whl[0][0][kc][0];
        __half* dl = (__half*)&g_whl[0][1][kc][0];
        for (int e = tid; e < 4096; e += 256) {   // e = n*32 + k
            int k = e & 31, n = e >> 5;
            float val = tile[k * 129 + n];
            __half hh = __float2half_rn(val);
            dh[e] = hh;
            dl[e] = __float2half_rn(val - __half2float(hh));
        }
    } else if (bid < 12) {
        // M half-chunk: rows a in [kc*32 + half*16, +16)
        const int kc = (bid - 4) >> 1, half = (bid - 4) & 1;
        const int a0 = kc * 32 + half * 16;
        float* sWq = sbuf;                     // [16][128]
        for (int e = tid; e < 2048; e += 256)
            sWq[e] = Wq[(a0 + (e >> 7)) * H_ + (e & 127)];
        __syncthreads();
        const int n = tid & 127, koff = (tid >> 7) * 8;
        float acc[8];
        #pragma unroll
        for (int t = 0; t < 8; t++) acc[t] = 0.f;
        const float4* wkn = (const float4*)(Wk + n * H_);
        for (int i = 0; i < 32; i++) {
            float4 kv = wkn[i];
            #pragma unroll
            for (int t = 0; t < 8; t++) {
                const float* q = sWq + (koff + t) * 128 + i * 4;
                acc[t] = fmaf(q[0], kv.x, fmaf(q[1], kv.y,
                          fmaf(q[2], kv.z, fmaf(q[3], kv.w, acc[t]))));
            }
        }
        __half* dh = (__half*)&g_whl[1][0][kc][0];
        __half* dl = (__half*)&g_whl[1][1][kc][0];
        #pragma unroll
        for (int t = 0; t < 8; t++) {
            int k_local = half * 16 + koff + t;
            int e = n * 32 + k_local;
            __half hh = __float2half_rn(acc[t]);
            dh[e] = hh;
            dl[e] = __float2half_rn(acc[t] - __half2float(hh));
        }
    } else if (bid < 16) {
        const int kc = bid - 12;
        __shared__ float sW2s[4096], sWv[4096];
        for (int e = tid; e < 4096; e += 256) {
            sW2s[e] = W2[e];                   // [128 n][32 c]
            sWv[e]  = Wv[(kc * 32 + (e >> 7)) * H_ + (e & 127)];  // [32 k][128 n]
        }
        __syncthreads();
        __half* dh = (__half*)&g_wv2[0][kc][0];
        __half* dl = (__half*)&g_wv2[1][kc][0];
        #pragma unroll
        for (int i = 0; i < 4; i++) {
            int o = tid + 256 * i;
            int k = o >> 5, cc = o & 31;
            float acc = 0.f;
            #pragma unroll 8
            for (int n = 0; n < 128; n++)
                acc = fmaf(sWv[k * 128 + n], sW2s[n * 32 + cc], acc);
            int e = cc * 32 + k;               // [c][k] layout
            __half hh = __float2half_rn(acc);
            dh[e] = hh;
            dl[e] = __float2half_rn(acc - __half2float(hh));
        }
    } else {
        if (tid < MID_) {
            float acc = b2[tid];
            for (int n = 0; n < 128; n++)
                acc = fmaf(bv[n], W2[n * 32 + tid], acc);
            g_cb2[tid] = acc;
        }
    }
}

// ---------------- main kernel ----------------
__global__ __launch_bounds__(NTHREADS, 2)
void exrest_fused_kernel(const float* __restrict__ x,  const float* __restrict__ b1,
                         const float* __restrict__ W3, const float* __restrict__ b3,
                         const float* __restrict__ pe,
                         float* __restrict__ out, float* __restrict__ wout)
{
    extern __shared__ float sm[];
    __half* Ah = (__half*)sm;
    __half* Al = (__half*)(sm + AL_F);
    const __half2* Ah2 = (const __half2*)sm;
    const __half2* Al2 = (const __half2*)(sm + AL_F);
    float* smS  = sm + SMS_F;                  // overlay on Ah rows 100..127
    float* cb2s = sm + SB2_F;
    float* sW3  = sm + SW3_F;
    float* sb3  = sm + SB3_F;

    const int tid  = threadIdx.x;
    const int lane = tid & 31;
    const int wid  = tid >> 5;                 // 0..7
    const int g    = lane >> 2;
    const int cq   = lane & 3;
    const int nhalf = wid >> 2;                // chunks 0-7: N 64-col half
    const int mrow  = (wid + 3 * nhalf) & 3;   // light (==3) warps spread
    const bool fullM = (mrow < 3);
    const int bb   = blockIdx.x;

    const uint32_t sbase = smem_u32(sm);
    const uint32_t ALOFSB = AL_F * 4;
    const uint32_t WLOFSB = 10240;             // hi image bytes in stage buf

    if (tid < MID_)        cb2s[tid] = g_cb2[tid];
    if (tid < MID_ * OUT_) sW3[tid] = W3[tid];
    if (tid < OUT_)        sb3[tid] = b3[tid];
    {
        const float* xb = x + (long long)bb * (S_ * IN_);
        for (int e = tid; e < 128 * 64; e += NTHREADS) {
            int r = e >> 6, cp = (e & 63) * 2;
            float2 v = make_float2(0.f, 0.f);
            if (r < S_ && cp < IN_)
                v = *(const float2*)(xb + r * IN_ + cp);   // (r*100+cp) even
            __half2 lo2;
            __half2 hi2 = split_hi2(v.x, v.y, lo2);
            *(__half2*)&Ah[r * SAH + cp] = hi2;
            *(__half2*)&Al[r * SAH + cp] = lo2;
        }
    }

    // staging: chunk nc -> buffer base (byte addr). nc 0..7: W1/M chunks;
    // nc 8..9: wv2 pairs (two kc per buffer: kc1 at +2560B).
    auto stage_chunk = [&](uint32_t base, int nc) {
        if (nc < 8) {
            #pragma unroll
            for (int i = 0; i < 4; i++) {
                int e = tid + 256 * i;
                int img = e >> 9, rem = e & 511;
                uint32_t d = base + (uint32_t)img * WLOFSB
                           + (uint32_t)(rem >> 2) * 80 + (uint32_t)(rem & 3) * 16;
                cp16(d, (const char*)&g_whl[nc >> 2][img][nc & 3][0] + rem * 16);
            }
        } else {
            int pair = nc - 8;
            #pragma unroll
            for (int i = 0; i < 2; i++) {
                int e = tid + 256 * i;
                int img = e >> 8, rem = e & 255;
                int kci = rem >> 7, r2 = rem & 127;
                uint32_t d = base + (uint32_t)img * WLOFSB + (uint32_t)kci * 2560
                           + (uint32_t)(r2 >> 2) * 80 + (uint32_t)(r2 & 3) * 16;
                cp16(d, (const char*)&g_wv2[img][pair * 2 + kci][0] + r2 * 16);
            }
        }
    };

    stage_chunk(sbase + WB_F * 4, 0);
    cp_commit();
    cp_wait0();
    __syncthreads();

    float c[2][8][4];
    #pragma unroll
    for (int mi = 0; mi < 2; mi++)
        #pragma unroll
        for (int nt = 0; nt < 8; nt++)
            #pragma unroll
            for (int rr = 0; rr < 4; rr++) c[mi][nt][rr] = 0.f;

    const float INV_SQRT_H = 0.08838834764831845f;

    const uint32_t aRowByte = (uint32_t)((mrow * 32 + (lane & 15)) * SAH
                                         + ((lane >> 4) << 3)) * 2;
    const uint32_t aRowByteP = (uint32_t)((wid * 16 + (lane & 15)) * SAH
                                          + ((lane >> 4) << 3)) * 2;
    const int bq = lane >> 3;
    const uint32_t bRowHalf = (uint32_t)((nhalf * 64 + ((bq >> 1) << 3) + (lane & 7)) * SWH
                                         + ((bq & 1) << 3));
    const uint32_t bRowHalfP = (uint32_t)((((bq >> 1) << 3) + (lane & 7)) * SWH
                                          + ((bq & 1) << 3));

    for (int cc = 0; cc < 10; cc++) {
        const int p = cc & 1;
        if (cc < 9) {
            stage_chunk(sbase + WB_F * 4 + (uint32_t)(1 - p) * 20480, cc + 1);
            cp_commit();
        }
        const uint32_t wbase = sbase + (uint32_t)WB_F * 4 + (uint32_t)p * 20480;

        if (cc < 8) {
            const int kc = cc & 3;
            #pragma unroll
            for (int ks = 0; ks < 2; ks++) {
                if (cc == 3 && ks == 1) continue;   // x cols 112-127 are zero
                const uint32_t aAddr = sbase + aRowByte + (uint32_t)(kc * 32 + ks * 16) * 2;
                uint32_t ah[2][4], al[2][4];
                ldm4(ah[0], aAddr);
                ldm4(al[0], aAddr + ALOFSB);
                if (fullM) {
                    ldm4(ah[1], aAddr + 16 * SAH * 2);
                    ldm4(al[1], aAddr + ALOFSB + 16 * SAH * 2);
                }
                #pragma unroll
                for (int gi = 0; gi < 4; gi++) {
                    const uint32_t bAddr = wbase
                        + (bRowHalf + (uint32_t)(gi * 16 * SWH) + (uint32_t)(ks * 16)) * 2;
                    uint32_t r4[4], s4[4];
                    ldm4(r4, bAddr);
                    ldm4(s4, bAddr + WLOFSB);
                    const int nt0 = gi * 2, nt1 = gi * 2 + 1;
                    mma_f16(c[0][nt0], ah[0], r4[0], r4[1]);
                    mma_f16(c[0][nt0], ah[0], s4[0], s4[1]);
                    mma_f16(c[0][nt0], al[0], r4[0], r4[1]);
                    mma_f16(c[0][nt1], ah[0], r4[2], r4[3]);
                    mma_f16(c[0][nt1], ah[0], s4[2], s4[3]);
                    mma_f16(c[0][nt1], al[0], r4[2], r4[3]);
                    if (fullM) {
                        mma_f16(c[1][nt0], ah[1], r4[0], r4[1]);
                        mma_f16(c[1][nt0], ah[1], s4[0], s4[1]);
                        mma_f16(c[1][nt0], al[1], r4[0], r4[1]);
                        mma_f16(c[1][nt1], ah[1], r4[2], r4[3]);
                        mma_f16(c[1][nt1], ah[1], s4[2], s4[3]);
                        mma_f16(c[1][nt1], al[1], r4[2], r4[3]);
                    }
                }
            }
        } else if (wid < 7) {                  // p = h @ W_v2 (N=32), 2 kc/chunk
            #pragma unroll
            for (int kci = 0; kci < 2; kci++) {
                const int kcp = (cc - 8) * 2 + kci;
                const uint32_t kbase = wbase + (uint32_t)kci * 2560;
                #pragma unroll
                for (int ks = 0; ks < 2; ks++) {
                    const uint32_t aAddr = sbase + aRowByteP
                                         + (uint32_t)(kcp * 32 + ks * 16) * 2;
                    uint32_t ah[4], al[4];
                    ldm4(ah, aAddr);
                    ldm4(al, aAddr + ALOFSB);
                    #pragma unroll
                    for (int gi = 0; gi < 2; gi++) {
                        const uint32_t bAddr = kbase
                            + (bRowHalfP + (uint32_t)(gi * 16 * SWH) + (uint32_t)(ks * 16)) * 2;
                        uint32_t r4[4], s4[4];
                        ldm4(r4, bAddr);
                        ldm4(s4, bAddr + WLOFSB);
                        const int nt0 = gi * 2, nt1 = gi * 2 + 1;
                        mma_f16(c[0][nt0], ah, r4[0], r4[1]);
                        mma_f16(c[0][nt0], ah, s4[0], s4[1]);
                        mma_f16(c[0][nt0], al, r4[0], r4[1]);
                        mma_f16(c[0][nt1], ah, r4[2], r4[3]);
                        mma_f16(c[0][nt1], ah, s4[2], s4[3]);
                        mma_f16(c[0][nt1], al, r4[2], r4[3]);
                    }
                }
            }
        }

        if (cc == 3) {
            __syncthreads();                   // all ldmatrix reads of A done
            #pragma unroll
            for (int mi = 0; mi < 2; mi++)
                #pragma unroll
                for (int hi = 0; hi < 2; hi++) {
                    int r = mrow * 32 + mi * 16 + hi * 8 + g;
                    if (r < S_) {
                        #pragma unroll
                        for (int nt = 0; nt < 8; nt++) {
                            int col = nhalf * 64 + nt * 8 + 2 * cq;
                            float2 bb1 = *(const float2*)(b1 + col);
                            float2 pp  = *(const float2*)(pe + r * H_ + col);
                            float v0 = c[mi][nt][hi * 2 + 0] + bb1.x;
                            float v1 = c[mi][nt][hi * 2 + 1] + bb1.y;
                            v0 = fmaxf(v0, 0.f) + pp.x;
                            v1 = fmaxf(v1, 0.f) + pp.y;
                            __half2 lo2;
                            __half2 hi2 = split_hi2(v0, v1, lo2);
                            *(__half2*)&Ah[r * SAH + col] = hi2;
                            *(__half2*)&Al[r * SAH + col] = lo2;
                        }
                    }
                }
            #pragma unroll
            for (int mi = 0; mi < 2; mi++)
                #pragma unroll
                for (int nt = 0; nt < 8; nt++)
                    #pragma unroll
                    for (int rr = 0; rr < 4; rr++) c[mi][nt][rr] = 0.f;
        } else if (cc == 7) {
            // t fragments -> banded scores vs h
            #pragma unroll
            for (int mi = 0; mi < 2; mi++)
                #pragma unroll
                for (int hi = 0; hi < 2; hi++) {
                    int r = mrow * 32 + mi * 16 + hi * 8 + g;
                    #pragma unroll
                    for (int m = 0; m < 5; m++) {
                        int j = r + 2 - m;
                        float pf = 0.f;
                        if (r < S_ && j >= 0 && j < S_) {
                            #pragma unroll
                            for (int nt = 0; nt < 8; nt++) {
                                int cw = nhalf * 32 + nt * 4 + cq;
                                float2 a2 = __half22float2(Ah2[j * 68 + cw]);
                                float2 l2 = __half22float2(Al2[j * 68 + cw]);
                                pf = fmaf(c[mi][nt][hi * 2 + 0], a2.x + l2.x, pf);
                                pf = fmaf(c[mi][nt][hi * 2 + 1], a2.y + l2.y, pf);
                            }
                        }
                        pf += __shfl_xor_sync(0xffffffffu, pf, 1);
                        pf += __shfl_xor_sync(0xffffffffu, pf, 2);
                        if (cq == 0 && r < S_)
                            smS[nhalf * 800 + r * 8 + m] = pf;
                    }
                }
            __syncthreads();
            if (tid < S_) {
                int s = tid;
                float sc[5];
                #pragma unroll
                for (int m = 0; m < 5; m++)
                    sc[m] = (smS[s * 8 + m] + smS[800 + s * 8 + m]) * INV_SQRT_H;
                float mx = sc[0];
                #pragma unroll
                for (int m = 1; m < 5; m++) mx = fmaxf(mx, sc[m]);
                float e5[5], sum = 0.f;
                #pragma unroll
                for (int m = 0; m < 5; m++) { e5[m] = __expf(sc[m] - mx); sum += e5[m]; }
                float rs = 1.f / sum;
                float* wp = wout + ((long long)bb * S_ + s) * 5;
                #pragma unroll
                for (int m = 0; m < 5; m++) {
                    float wmm = e5[m] * rs;
                    wp[m] = wmm;
                    smS[s * 8 + m] = wmm;
                }
            }
            #pragma unroll
            for (int mi = 0; mi < 2; mi++)
                #pragma unroll
                for (int nt = 0; nt < 8; nt++)
                    #pragma unroll
                    for (int rr = 0; rr < 4; rr++) c[mi][nt][rr] = 0.f;
        }

        cp_wait0();
        __syncthreads();
    }

    // ---- p epilogue: write p fp32 into (now free) staging region ----
    float* pbuf = sm + WB_F;                   // [100][stride 33]
    if (wid < 7) {
        #pragma unroll
        for (int hi = 0; hi < 2; hi++) {
            int r = wid * 16 + hi * 8 + g;
            if (r < S_) {
                #pragma unroll
                for (int nt = 0; nt < 4; nt++) {
                    int col = nt * 8 + 2 * cq;
                    pbuf[r * 33 + col]     = c[0][nt][hi * 2 + 0];
                    pbuf[r * 33 + col + 1] = c[0][nt][hi * 2 + 1];
                }
            }
        }
    }
    __syncthreads();

    // ---- final: mid = relu(banded avg of p + cb2); out = mid @ W3 + b3 ----
    const float w3a = sW3[lane * 2 + 0];
    const float w3b = sW3[lane * 2 + 1];
    const float cb2l = cb2s[lane];
    const float b30 = sb3[0], b31 = sb3[1];

    for (int s = wid; s < S_; s += 8) {
        float mid = cb2l;
        #pragma unroll
        for (int m = 0; m < 5; m++) {
            int j = s + 2 - m;
            if (j >= 0 && j < S_)
                mid = fmaf(smS[s * 8 + m], pbuf[j * 33 + lane], mid);
        }
        mid = fmaxf(mid, 0.f);
        float p0 = mid * w3a;
        float p1 = mid * w3b;
        #pragma unroll
        for (int off = 16; off > 0; off >>= 1) {
            p0 += __shfl_xor_sync(0xffffffffu, p0, off);
            p1 += __shfl_xor_sync(0xffffffffu, p1, off);
        }
        if (lane == 0) {
            float* op = out + ((long long)bb * S_ + s) * 2;
            op[0] = p0 + b30;
            op[1] = p1 + b31;
        }
    }
}

extern "C" void kernel_launch(void* const* d_in, const int* in_sizes, int n_in,
                              void* d_out, int out_size)
{
    const float* x  = (const float*)d_in[0];
    const float* W1 = (const float*)d_in[1];
    const float* b1 = (const float*)d_in[2];
    const float* Wq = (const float*)d_in[3];
    const float* Wk = (const float*)d_in[4];
    const float* Wv = (const float*)d_in[5];
    const float* bv = (const float*)d_in[6];
    const float* W2 = (const float*)d_in[7];
    const float* b2 = (const float*)d_in[8];
    const float* W3 = (const float*)d_in[9];
    const float* b3 = (const float*)d_in[10];
    const float* pe = (const float*)d_in[11];

    float* out  = (float*)d_out;                    // (B,S,2)
    float* wout = out + (long long)B_ * S_ * OUT_;  // (B,S,1,5)

    cudaFuncSetAttribute(exrest_fused_kernel,
                         cudaFuncAttributeMaxDynamicSharedMemorySize, SMEM_BYTES);

    prep_all<<<17, 256>>>(W1, Wq, Wk, Wv, W2, bv, b2);
    exrest_fused_kernel<<<B_, NTHREADS, SMEM_BYTES>>>(
        x, b1, W3, b3, pe, out, wout);
}